// round 3
// baseline (speedup 1.0000x reference)
#include <cuda_runtime.h>

// Problem constants
#define B_    4
#define M_    4096
#define DM_   1024
#define H_    16
#define HD_   64
#define SEG_  128
#define NSEG_ 32          // M_/SEG_
#define SCALE_ 0.125f     // HD^-0.5

// Scratch (device globals: allocation-free per harness rules)
__device__ float g_qkv[(size_t)3 * B_ * H_ * M_ * HD_];   // [which][b][h][m][d]  ~201 MB
__device__ float g_att[(size_t)B_ * M_ * DM_];            // [b][m][h*64+d]       ~64 MB

// ---------------------------------------------------------------------------
// SGEMM: C = A(MxK) * Bw(NxK)^T, K=1024, tiles 128x128x8, 256 thr, 8x8/thread
// ---------------------------------------------------------------------------
__global__ __launch_bounds__(256) void sgemm_qkv_kernel(const float* __restrict__ A,
                                                        const float* __restrict__ Bw) {
    const int K = 1024;
    __shared__ float As[8][128];
    __shared__ float Bs[8][128];
    int tid = threadIdx.x;
    int m0 = blockIdx.y * 128;
    int n0 = blockIdx.x * 128;
    int lrow = tid >> 1;
    int lcol = (tid & 1) << 2;
    const float* Ap = A  + (size_t)(m0 + lrow) * K + lcol;
    const float* Bp = Bw + (size_t)(n0 + lrow) * K + lcol;
    int tm = (tid >> 4) << 3;
    int tn = (tid & 15) << 3;
    float acc[8][8];
#pragma unroll
    for (int i = 0; i < 8; i++)
#pragma unroll
        for (int j = 0; j < 8; j++) acc[i][j] = 0.f;

    for (int k0 = 0; k0 < K; k0 += 8) {
        float4 av = *(const float4*)(Ap + k0);
        float4 bv = *(const float4*)(Bp + k0);
        __syncthreads();
        As[lcol + 0][lrow] = av.x; As[lcol + 1][lrow] = av.y;
        As[lcol + 2][lrow] = av.z; As[lcol + 3][lrow] = av.w;
        Bs[lcol + 0][lrow] = bv.x; Bs[lcol + 1][lrow] = bv.y;
        Bs[lcol + 2][lrow] = bv.z; Bs[lcol + 3][lrow] = bv.w;
        __syncthreads();
#pragma unroll
        for (int kk = 0; kk < 8; kk++) {
            float a[8], b[8];
            *(float4*)&a[0] = *(const float4*)&As[kk][tm];
            *(float4*)&a[4] = *(const float4*)&As[kk][tm + 4];
            *(float4*)&b[0] = *(const float4*)&Bs[kk][tn];
            *(float4*)&b[4] = *(const float4*)&Bs[kk][tn + 4];
#pragma unroll
            for (int i = 0; i < 8; i++)
#pragma unroll
                for (int j = 0; j < 8; j++) acc[i][j] += a[i] * b[j];
        }
    }

    // Scatter epilogue: col -> (which, h, d); row -> (b, m). 8-col tile never
    // crosses a 64-boundary (tn multiple of 8), so which/h/d0 constant here.
    int col0  = n0 + tn;
    int which = col0 >> 10;
    int hh    = (col0 & 1023) >> 6;
    int d0    = col0 & 63;
#pragma unroll
    for (int i = 0; i < 8; i++) {
        int row = m0 + tm + i;
        int bb = row >> 12;
        int mm = row & 4095;
        size_t base = ((((size_t)which * B_ + bb) * H_ + hh) * M_ + mm) * HD_ + d0;
        *(float4*)&g_qkv[base]     = make_float4(acc[i][0], acc[i][1], acc[i][2], acc[i][3]);
        *(float4*)&g_qkv[base + 4] = make_float4(acc[i][4], acc[i][5], acc[i][6], acc[i][7]);
    }
}

__global__ __launch_bounds__(256) void sgemm_out_kernel(const float* __restrict__ Bw,
                                                        float* __restrict__ C) {
    const int K = 1024;
    __shared__ float As[8][128];
    __shared__ float Bs[8][128];
    int tid = threadIdx.x;
    int m0 = blockIdx.y * 128;
    int n0 = blockIdx.x * 128;
    int lrow = tid >> 1;
    int lcol = (tid & 1) << 2;
    const float* Ap = g_att + (size_t)(m0 + lrow) * K + lcol;
    const float* Bp = Bw    + (size_t)(n0 + lrow) * K + lcol;
    int tm = (tid >> 4) << 3;
    int tn = (tid & 15) << 3;
    float acc[8][8];
#pragma unroll
    for (int i = 0; i < 8; i++)
#pragma unroll
        for (int j = 0; j < 8; j++) acc[i][j] = 0.f;

    for (int k0 = 0; k0 < K; k0 += 8) {
        float4 av = *(const float4*)(Ap + k0);
        float4 bv = *(const float4*)(Bp + k0);
        __syncthreads();
        As[lcol + 0][lrow] = av.x; As[lcol + 1][lrow] = av.y;
        As[lcol + 2][lrow] = av.z; As[lcol + 3][lrow] = av.w;
        Bs[lcol + 0][lrow] = bv.x; Bs[lcol + 1][lrow] = bv.y;
        Bs[lcol + 2][lrow] = bv.z; Bs[lcol + 3][lrow] = bv.w;
        __syncthreads();
#pragma unroll
        for (int kk = 0; kk < 8; kk++) {
            float a[8], b[8];
            *(float4*)&a[0] = *(const float4*)&As[kk][tm];
            *(float4*)&a[4] = *(const float4*)&As[kk][tm + 4];
            *(float4*)&b[0] = *(const float4*)&Bs[kk][tn];
            *(float4*)&b[4] = *(const float4*)&Bs[kk][tn + 4];
#pragma unroll
            for (int i = 0; i < 8; i++)
#pragma unroll
                for (int j = 0; j < 8; j++) acc[i][j] += a[i] * b[j];
        }
    }
#pragma unroll
    for (int i = 0; i < 8; i++) {
        int row = m0 + tm + i;
        int col = n0 + tn;   // FIX: was missing n0 — blocks overwrote cols 0..127
        *(float4*)&C[(size_t)row * 1024 + col]     = make_float4(acc[i][0], acc[i][1], acc[i][2], acc[i][3]);
        *(float4*)&C[(size_t)row * 1024 + col + 4] = make_float4(acc[i][4], acc[i][5], acc[i][6], acc[i][7]);
    }
}

// ---------------------------------------------------------------------------
// Attention: one CTA per (segment s, head h, batch b). 256 threads.
// K tile = 64 dilated keys x 64 dims; 2 query blocks of 64.
// Quirk (faithful to reference): c[t] = max over the 64 queries of the block,
// w = exp(score - c[t]); out = (w @ V) / (1e-10 + rowsum(w)).
// ---------------------------------------------------------------------------
__global__ __launch_bounds__(256) void hilbert_attn_kernel(const int* __restrict__ hmap) {
    extern __shared__ float sm[];
    float (*Qs)[65] = (float (*)[65])(sm);
    float (*Ks)[65] = (float (*)[65])(sm + 64 * 65);
    float (*Vs)[65] = (float (*)[65])(sm + 2 * 64 * 65);
    float (*Ss)[65] = (float (*)[65])(sm + 3 * 64 * 65);
    __shared__ float cmax[64];
    __shared__ float dsum[64];
    __shared__ int   kposs[64];

    int s = blockIdx.x, h = blockIdx.y, b = blockIdx.z;
    int tid = threadIdx.x;

    size_t qbase = (((size_t)0 * B_ + b) * H_ + h) * (size_t)M_ * HD_;
    size_t kbase = (((size_t)1 * B_ + b) * H_ + h) * (size_t)M_ * HD_;
    size_t vbase = (((size_t)2 * B_ + b) * H_ + h) * (size_t)M_ * HD_;

    if (tid < 64) kposs[tid] = hmap[s * SEG_ + tid * 2];   // dilation 2
    __syncthreads();

    for (int idx = tid; idx < 64 * 64; idx += 256) {
        int r = idx >> 6, d = idx & 63;
        int p = kposs[r];
        Ks[r][d] = g_qkv[kbase + (size_t)p * HD_ + d];
        Vs[r][d] = g_qkv[vbase + (size_t)p * HD_ + d];
    }

    int q0 = (tid >> 4) << 2;   // 16 query groups of 4
    int t0 = (tid & 15) << 2;   // 16 key/dim groups of 4

    for (int n = 0; n < 2; n++) {
        __syncthreads();   // prev iter fully done; K/V loads visible
        for (int idx = tid; idx < 64 * 64; idx += 256) {
            int r = idx >> 6, d = idx & 63;
            int p = hmap[s * SEG_ + n * 64 + r];
            Qs[r][d] = g_qkv[qbase + (size_t)p * HD_ + d] * SCALE_;
        }
        __syncthreads();

        // scores: 4x4 per thread
        float acc[4][4];
#pragma unroll
        for (int i = 0; i < 4; i++)
#pragma unroll
            for (int j = 0; j < 4; j++) acc[i][j] = 0.f;
#pragma unroll 8
        for (int kk = 0; kk < 64; kk++) {
            float qa[4], kb[4];
#pragma unroll
            for (int i = 0; i < 4; i++) qa[i] = Qs[q0 + i][kk];
#pragma unroll
            for (int j = 0; j < 4; j++) kb[j] = Ks[t0 + j][kk];
#pragma unroll
            for (int i = 0; i < 4; i++)
#pragma unroll
                for (int j = 0; j < 4; j++) acc[i][j] += qa[i] * kb[j];
        }
#pragma unroll
        for (int i = 0; i < 4; i++)
#pragma unroll
            for (int j = 0; j < 4; j++) Ss[q0 + i][t0 + j] = acc[i][j];
        __syncthreads();

        if (tid < 64) {   // per-key max over the 64-query block
            float mx = -1e30f;
#pragma unroll 8
            for (int q = 0; q < 64; q++) mx = fmaxf(mx, Ss[q][tid]);
            cmax[tid] = mx;
        }
        __syncthreads();

#pragma unroll
        for (int i = 0; i < 4; i++)
#pragma unroll
            for (int j = 0; j < 4; j++)
                Ss[q0 + i][t0 + j] = __expf(acc[i][j] - cmax[t0 + j]);
        __syncthreads();

        if (tid < 64) {   // per-query denominator
            float sum = 1e-10f;
#pragma unroll 8
            for (int t = 0; t < 64; t++) sum += Ss[tid][t];
            dsum[tid] = sum;
        }
        __syncthreads();

        // out = w @ V, 4 queries x 4 dims per thread
        float oac[4][4];
#pragma unroll
        for (int i = 0; i < 4; i++)
#pragma unroll
            for (int j = 0; j < 4; j++) oac[i][j] = 0.f;
#pragma unroll 8
        for (int t = 0; t < 64; t++) {
            float wa[4], vb[4];
#pragma unroll
            for (int i = 0; i < 4; i++) wa[i] = Ss[q0 + i][t];
#pragma unroll
            for (int j = 0; j < 4; j++) vb[j] = Vs[t][t0 + j];
#pragma unroll
            for (int i = 0; i < 4; i++)
#pragma unroll
                for (int j = 0; j < 4; j++) oac[i][j] += wa[i] * vb[j];
        }
#pragma unroll
        for (int i = 0; i < 4; i++) {
            int q = q0 + i;
            float inv = 1.0f / dsum[q];
            int m = s * SEG_ + n * 64 + q;                  // linear output position
            size_t o = ((size_t)(b * M_ + m)) * DM_ + h * HD_ + t0;
            g_att[o + 0] = oac[i][0] * inv;
            g_att[o + 1] = oac[i][1] * inv;
            g_att[o + 2] = oac[i][2] * inv;
            g_att[o + 3] = oac[i][3] * inv;
        }
    }
}

// ---------------------------------------------------------------------------

extern "C" void kernel_launch(void* const* d_in, const int* in_sizes, int n_in,
                              void* d_out, int out_size) {
    const float* x    = (const float*)d_in[0];
    const float* Wqkv = (const float*)d_in[1];
    const float* Wout = (const float*)d_in[2];
    const int*   hmap = (const int*)d_in[3];
    float* out = (float*)d_out;
    (void)in_sizes; (void)n_in; (void)out_size;

    // 1) QKV projection: [16384,1024] x [3072,1024]^T, scatter into q/k/v
    sgemm_qkv_kernel<<<dim3(24, 128), 256>>>(x, Wqkv);

    // 2) Hilbert segmented attention (2048 CTAs)
    const int smem = 4 * 64 * 65 * (int)sizeof(float);   // 66560 B > 48K: opt in
    cudaFuncSetAttribute((const void*)hilbert_attn_kernel,
                         cudaFuncAttributeMaxDynamicSharedMemorySize, smem);
    hilbert_attn_kernel<<<dim3(NSEG_, H_, B_), 256, smem>>>(hmap);

    // 3) Output projection: [16384,1024] x [1024,1024]^T
    sgemm_out_kernel<<<dim3(8, 128), 256>>>(Wout, out);
}

// round 6
// speedup vs baseline: 2.9973x; 2.9973x over previous
#include <cuda_runtime.h>
#include <cuda_bf16.h>
#include <cstdint>

// Problem constants
#define B_    4
#define M_    4096
#define DM_   1024
#define H_    16
#define HD_   64
#define SEG_  128
#define NSEG_ 32
#define SCALE_ 0.125f
#define KDIM  1024

// ---------------------------------------------------------------------------
// Scratch (device globals: allocation-free per harness rules)
// ---------------------------------------------------------------------------
__device__ float g_qkv[(size_t)3 * B_ * H_ * M_ * HD_];            // fp32 q/k/v
__device__ __nv_bfloat16 g_x_hi[(size_t)B_ * M_ * DM_];
__device__ __nv_bfloat16 g_x_lo[(size_t)B_ * M_ * DM_];
__device__ __nv_bfloat16 g_wqkv_hi[3 * DM_ * DM_];
__device__ __nv_bfloat16 g_wqkv_lo[3 * DM_ * DM_];
__device__ __nv_bfloat16 g_wout_hi[DM_ * DM_];
__device__ __nv_bfloat16 g_wout_lo[DM_ * DM_];
__device__ __nv_bfloat16 g_att_hi[(size_t)B_ * M_ * DM_];
__device__ __nv_bfloat16 g_att_lo[(size_t)B_ * M_ * DM_];

// ---------------------------------------------------------------------------
// Helpers (compute_103-safe: no tcgen05/TMEM — those are sm_103a-gated PTX)
// ---------------------------------------------------------------------------
__device__ __forceinline__ uint32_t smem_to_u32(const void* p) {
    uint32_t a;
    asm("{ .reg .u64 t; cvta.to.shared.u64 t, %1; cvt.u32.u64 %0, t; }" : "=r"(a) : "l"(p));
    return a;
}
#define SWZ128(o) ((o) ^ (((o) >> 3) & 0x70))

__device__ __forceinline__ void cp_async16(uint32_t s, const void* g) {
    asm volatile("cp.async.cg.shared.global [%0], [%1], 16;" :: "r"(s), "l"(g));
}
__device__ __forceinline__ void ldsm_x4(uint32_t* r, uint32_t addr) {
    asm volatile("ldmatrix.sync.aligned.m8n8.x4.shared.b16 {%0,%1,%2,%3}, [%4];"
                 : "=r"(r[0]), "=r"(r[1]), "=r"(r[2]), "=r"(r[3]) : "r"(addr));
}
__device__ __forceinline__ void mma16816(float* d, const uint32_t* a, const uint32_t* b) {
    asm volatile("mma.sync.aligned.m16n8k16.row.col.f32.bf16.bf16.f32 "
                 "{%0,%1,%2,%3}, {%4,%5,%6,%7}, {%8,%9}, {%0,%1,%2,%3};"
                 : "+f"(d[0]), "+f"(d[1]), "+f"(d[2]), "+f"(d[3])
                 : "r"(a[0]), "r"(a[1]), "r"(a[2]), "r"(a[3]), "r"(b[0]), "r"(b[1]));
}

// ---------------------------------------------------------------------------
// fp32 -> (hi, lo) bf16 split
// ---------------------------------------------------------------------------
__global__ __launch_bounds__(256) void split_kernel(const float* __restrict__ in,
                                                    __nv_bfloat16* __restrict__ hi,
                                                    __nv_bfloat16* __restrict__ lo, int n) {
    int i = (blockIdx.x * 256 + threadIdx.x) * 4;
    if (i >= n) return;
    float4 v = *(const float4*)(in + i);
    __nv_bfloat16 h0 = __float2bfloat16(v.x), h1 = __float2bfloat16(v.y);
    __nv_bfloat16 h2 = __float2bfloat16(v.z), h3 = __float2bfloat16(v.w);
    __nv_bfloat16 l0 = __float2bfloat16(v.x - __bfloat162float(h0));
    __nv_bfloat16 l1 = __float2bfloat16(v.y - __bfloat162float(h1));
    __nv_bfloat16 l2 = __float2bfloat16(v.z - __bfloat162float(h2));
    __nv_bfloat16 l3 = __float2bfloat16(v.w - __bfloat162float(h3));
    *(__nv_bfloat162*)(hi + i)     = __nv_bfloat162(h0, h1);
    *(__nv_bfloat162*)(hi + i + 2) = __nv_bfloat162(h2, h3);
    *(__nv_bfloat162*)(lo + i)     = __nv_bfloat162(l0, l1);
    *(__nv_bfloat162*)(lo + i + 2) = __nv_bfloat162(l2, l3);
}

// ---------------------------------------------------------------------------
// Tensor-core GEMM via mma.sync: C[M,N] = A[M,K] * B[N,K]^T, K=1024,
// bf16 3-term error-compensated split, fp32 accum.
// CTA tile 128x128, K-chunk 64; 8 warps as 2(M) x 4(N), warp tile 64x32.
// smem: 4 tiles of 128 rows x 128B (SW128 swizzle) = 64 KB; 2 CTAs/SM.
// epi_mode 0: scatter into g_qkv; 1: plain fp32 write to Cout.
// ---------------------------------------------------------------------------
#define GEMM_SMEM 65536

__global__ __launch_bounds__(256, 2) void gemm_tc_kernel(
    const __nv_bfloat16* __restrict__ Ahi, const __nv_bfloat16* __restrict__ Alo,
    const __nv_bfloat16* __restrict__ Bhi, const __nv_bfloat16* __restrict__ Blo,
    float* __restrict__ Cout, int epi_mode) {
    extern __shared__ char sm[];
    const uint32_t smb = smem_to_u32(sm);
    const int tid = threadIdx.x;
    const int wid = tid >> 5, lane = tid & 31;
    const int wm = wid & 1, wn = wid >> 1;
    const int m0 = blockIdx.y * 128, n0 = blockIdx.x * 128;

    // smem tile bases: 0=A_hi 1=A_lo 2=B_hi 3=B_lo
    const uint32_t tb[4] = {smb, smb + 16384u, smb + 32768u, smb + 49152u};

    float acc[4][4][4];
#pragma unroll
    for (int mi = 0; mi < 4; mi++)
#pragma unroll
        for (int ni = 0; ni < 4; ni++)
#pragma unroll
            for (int e = 0; e < 4; e++) acc[mi][ni][e] = 0.f;

    // per-thread fragment address components
    const int a_row = wm * 64 + (lane & 15);           // + mi*16
    const int a_kb  = (lane >> 4) << 4;                // + ks*32
    const int b_row = wn * 32 + ((lane >> 4) << 3) + (lane & 7);   // + p*16
    const int b_kb  = ((lane >> 3) & 1) << 4;          // + ks*32

    for (int c = 0; c < 16; c++) {
        // ---- load 4 tiles (16 cp.async x 16B per thread) ----
#pragma unroll
        for (int tile = 0; tile < 4; tile++) {
            const __nv_bfloat16* src = (tile == 0) ? Ahi : (tile == 1) ? Alo
                                      : (tile == 2) ? Bhi : Blo;
            const int rbase = (tile < 2) ? m0 : n0;
#pragma unroll
            for (int tt = 0; tt < 4; tt++) {
                int w = tt * 256 + tid;
                int row = w >> 3, g = (w & 7) << 4;
                const char* gp = (const char*)src
                               + ((size_t)(rbase + row) * KDIM + (size_t)c * 64) * 2 + g;
                uint32_t off = (uint32_t)(row * 128 + g);
                cp_async16(tb[tile] + SWZ128(off), gp);
            }
        }
        asm volatile("cp.async.commit_group;" ::: "memory");
        asm volatile("cp.async.wait_group 0;" ::: "memory");
        __syncthreads();

        // ---- compute: 4 k16 steps, 3 split terms ----
#pragma unroll
        for (int ks = 0; ks < 4; ks++) {
            uint32_t af[4][4], bhf[2][4], blf[2][4];
#pragma unroll
            for (int mi = 0; mi < 4; mi++) {
                uint32_t off = (uint32_t)((a_row + mi * 16) * 128 + ks * 32 + a_kb);
                ldsm_x4(af[mi], tb[0] + SWZ128(off));
            }
#pragma unroll
            for (int p = 0; p < 2; p++) {
                uint32_t off = (uint32_t)((b_row + p * 16) * 128 + ks * 32 + b_kb);
                ldsm_x4(bhf[p], tb[2] + SWZ128(off));
                ldsm_x4(blf[p], tb[3] + SWZ128(off));
            }
#pragma unroll
            for (int mi = 0; mi < 4; mi++)
#pragma unroll
                for (int ni = 0; ni < 4; ni++) {
                    mma16816(acc[mi][ni], af[mi], &bhf[ni >> 1][(ni & 1) * 2]);  // hi*hi
                    mma16816(acc[mi][ni], af[mi], &blf[ni >> 1][(ni & 1) * 2]);  // hi*lo
                }
#pragma unroll
            for (int mi = 0; mi < 4; mi++) {   // reload A as lo (overwrite hi frags)
                uint32_t off = (uint32_t)((a_row + mi * 16) * 128 + ks * 32 + a_kb);
                ldsm_x4(af[mi], tb[1] + SWZ128(off));
            }
#pragma unroll
            for (int mi = 0; mi < 4; mi++)
#pragma unroll
                for (int ni = 0; ni < 4; ni++)
                    mma16816(acc[mi][ni], af[mi], &bhf[ni >> 1][(ni & 1) * 2]);  // lo*hi
        }
        __syncthreads();   // before next chunk overwrites smem
    }

    // ---- epilogue ----
    const int ml = wm * 64 + (lane >> 2);
    const int nl = wn * 32 + ((lane & 3) << 1);
#pragma unroll
    for (int mi = 0; mi < 4; mi++)
#pragma unroll
        for (int ni = 0; ni < 4; ni++)
#pragma unroll
            for (int half = 0; half < 2; half++) {
                int row = m0 + ml + mi * 16 + half * 8;
                int col = n0 + nl + ni * 8;
                float2 v = make_float2(acc[mi][ni][half * 2], acc[mi][ni][half * 2 + 1]);
                if (epi_mode == 0) {
                    int which = col >> 10, hh = (col & 1023) >> 6, d0 = col & 63;
                    int bb = row >> 12, mm = row & 4095;
                    size_t base = ((((size_t)which * B_ + bb) * H_ + hh) * (size_t)M_ + mm)
                                  * HD_ + d0;
                    *(float2*)&g_qkv[base] = v;
                } else {
                    *(float2*)&Cout[(size_t)row * 1024 + col] = v;
                }
            }
}

// ---------------------------------------------------------------------------
// Attention: one CTA per (segment, head, batch). Faithful reference quirk.
// Emits bf16 hi/lo split directly for the output-projection GEMM.
// ---------------------------------------------------------------------------
__global__ __launch_bounds__(256) void hilbert_attn_kernel(const int* __restrict__ hmap) {
    extern __shared__ float smf[];
    float (*Qs)[65] = (float (*)[65])(smf);
    float (*Ks)[65] = (float (*)[65])(smf + 64 * 65);
    float (*Vs)[65] = (float (*)[65])(smf + 2 * 64 * 65);
    float (*Ss)[65] = (float (*)[65])(smf + 3 * 64 * 65);
    __shared__ float cmax[64];
    __shared__ float dsum[64];
    __shared__ int   kposs[64];

    int s = blockIdx.x, h = blockIdx.y, b = blockIdx.z;
    int tid = threadIdx.x;

    size_t qbase = (((size_t)0 * B_ + b) * H_ + h) * (size_t)M_ * HD_;
    size_t kbase = (((size_t)1 * B_ + b) * H_ + h) * (size_t)M_ * HD_;
    size_t vbase = (((size_t)2 * B_ + b) * H_ + h) * (size_t)M_ * HD_;

    if (tid < 64) kposs[tid] = hmap[s * SEG_ + tid * 2];
    __syncthreads();

    for (int idx = tid; idx < 64 * 64; idx += 256) {
        int r = idx >> 6, d = idx & 63;
        int p = kposs[r];
        Ks[r][d] = g_qkv[kbase + (size_t)p * HD_ + d];
        Vs[r][d] = g_qkv[vbase + (size_t)p * HD_ + d];
    }

    int q0 = (tid >> 4) << 2;
    int t0 = (tid & 15) << 2;

    for (int n = 0; n < 2; n++) {
        __syncthreads();
        for (int idx = tid; idx < 64 * 64; idx += 256) {
            int r = idx >> 6, d = idx & 63;
            int p = hmap[s * SEG_ + n * 64 + r];
            Qs[r][d] = g_qkv[qbase + (size_t)p * HD_ + d] * SCALE_;
        }
        __syncthreads();

        float acc[4][4];
#pragma unroll
        for (int i = 0; i < 4; i++)
#pragma unroll
            for (int j = 0; j < 4; j++) acc[i][j] = 0.f;
#pragma unroll 8
        for (int kk = 0; kk < 64; kk++) {
            float qa[4], kb[4];
#pragma unroll
            for (int i = 0; i < 4; i++) qa[i] = Qs[q0 + i][kk];
#pragma unroll
            for (int j = 0; j < 4; j++) kb[j] = Ks[t0 + j][kk];
#pragma unroll
            for (int i = 0; i < 4; i++)
#pragma unroll
                for (int j = 0; j < 4; j++) acc[i][j] += qa[i] * kb[j];
        }
#pragma unroll
        for (int i = 0; i < 4; i++)
#pragma unroll
            for (int j = 0; j < 4; j++) Ss[q0 + i][t0 + j] = acc[i][j];
        __syncthreads();

        if (tid < 64) {
            float mx = -1e30f;
#pragma unroll 8
            for (int q = 0; q < 64; q++) mx = fmaxf(mx, Ss[q][tid]);
            cmax[tid] = mx;
        }
        __syncthreads();

#pragma unroll
        for (int i = 0; i < 4; i++)
#pragma unroll
            for (int j = 0; j < 4; j++)
                Ss[q0 + i][t0 + j] = __expf(acc[i][j] - cmax[t0 + j]);
        __syncthreads();

        if (tid < 64) {
            float sum = 1e-10f;
#pragma unroll 8
            for (int t = 0; t < 64; t++) sum += Ss[tid][t];
            dsum[tid] = sum;
        }
        __syncthreads();

        float oac[4][4];
#pragma unroll
        for (int i = 0; i < 4; i++)
#pragma unroll
            for (int j = 0; j < 4; j++) oac[i][j] = 0.f;
#pragma unroll 8
        for (int t = 0; t < 64; t++) {
            float wa[4], vb[4];
#pragma unroll
            for (int i = 0; i < 4; i++) wa[i] = Ss[q0 + i][t];
#pragma unroll
            for (int j = 0; j < 4; j++) vb[j] = Vs[t][t0 + j];
#pragma unroll
            for (int i = 0; i < 4; i++)
#pragma unroll
                for (int j = 0; j < 4; j++) oac[i][j] += wa[i] * vb[j];
        }
#pragma unroll
        for (int i = 0; i < 4; i++) {
            int q = q0 + i;
            float inv = 1.0f / dsum[q];
            int m = s * SEG_ + n * 64 + q;
            size_t o = ((size_t)(b * M_ + m)) * DM_ + h * HD_ + t0;
#pragma unroll
            for (int j = 0; j < 4; j++) {
                float v = oac[i][j] * inv;
                __nv_bfloat16 hv = __float2bfloat16(v);
                g_att_hi[o + j] = hv;
                g_att_lo[o + j] = __float2bfloat16(v - __bfloat162float(hv));
            }
        }
    }
}

// ---------------------------------------------------------------------------

extern "C" void kernel_launch(void* const* d_in, const int* in_sizes, int n_in,
                              void* d_out, int out_size) {
    const float* x    = (const float*)d_in[0];
    const float* Wqkv = (const float*)d_in[1];
    const float* Wout = (const float*)d_in[2];
    const int*   hmap = (const int*)d_in[3];
    float* out = (float*)d_out;
    (void)in_sizes; (void)n_in; (void)out_size;

    __nv_bfloat16 *xh, *xl, *qh, *ql, *oh, *ol, *ah, *al;
    cudaGetSymbolAddress((void**)&xh, g_x_hi);    cudaGetSymbolAddress((void**)&xl, g_x_lo);
    cudaGetSymbolAddress((void**)&qh, g_wqkv_hi); cudaGetSymbolAddress((void**)&ql, g_wqkv_lo);
    cudaGetSymbolAddress((void**)&oh, g_wout_hi); cudaGetSymbolAddress((void**)&ol, g_wout_lo);
    cudaGetSymbolAddress((void**)&ah, g_att_hi);  cudaGetSymbolAddress((void**)&al, g_att_lo);

    // 0) bf16 hi/lo splits
    split_kernel<<<(B_ * M_ * DM_) / 1024, 256>>>(x, xh, xl, B_ * M_ * DM_);
    split_kernel<<<(3 * DM_ * DM_) / 1024, 256>>>(Wqkv, qh, ql, 3 * DM_ * DM_);
    split_kernel<<<(DM_ * DM_) / 1024, 256>>>(Wout, oh, ol, DM_ * DM_);

    cudaFuncSetAttribute((const void*)gemm_tc_kernel,
                         cudaFuncAttributeMaxDynamicSharedMemorySize, GEMM_SMEM);

    // 1) QKV projection: [16384,1024] x [3072,1024]^T -> g_qkv (scatter)
    gemm_tc_kernel<<<dim3(24, 128), 256, GEMM_SMEM>>>(xh, xl, qh, ql, nullptr, 0);

    // 2) Hilbert segmented attention (writes bf16 hi/lo)
    const int smem = 4 * 64 * 65 * (int)sizeof(float);
    cudaFuncSetAttribute((const void*)hilbert_attn_kernel,
                         cudaFuncAttributeMaxDynamicSharedMemorySize, smem);
    hilbert_attn_kernel<<<dim3(NSEG_, H_, B_), 256, smem>>>(hmap);

    // 3) Output projection: [16384,1024] x [1024,1024]^T -> out
    gemm_tc_kernel<<<dim3(8, 128), 256, GEMM_SMEM>>>(ah, al, oh, ol, out, 1);
}

// round 7
// speedup vs baseline: 3.8976x; 1.3004x over previous
#include <cuda_runtime.h>
#include <cuda_fp16.h>
#include <cstdint>

// Problem constants
#define B_    4
#define M_    4096
#define DM_   1024
#define H_    16
#define HD_   64
#define SEG_  128
#define NSEG_ 32
#define SCALE_ 0.125f
#define KDIM  1024

// ---------------------------------------------------------------------------
// Scratch (device globals: allocation-free per harness rules)
// ---------------------------------------------------------------------------
__device__ float g_qkv[(size_t)3 * B_ * H_ * M_ * HD_];   // fp32 q/k/v
__device__ __half g_x_hi[(size_t)B_ * M_ * DM_];
__device__ __half g_x_lo[(size_t)B_ * M_ * DM_];
__device__ __half g_wqkv_h[3 * DM_ * DM_];
__device__ __half g_wout_h[DM_ * DM_];
__device__ __half g_att_hi[(size_t)B_ * M_ * DM_];
__device__ __half g_att_lo[(size_t)B_ * M_ * DM_];

// ---------------------------------------------------------------------------
// Helpers (compute_103-safe: no tcgen05/TMEM — those are sm_103a-gated PTX)
// ---------------------------------------------------------------------------
__device__ __forceinline__ uint32_t smem_to_u32(const void* p) {
    uint32_t a;
    asm("{ .reg .u64 t; cvta.to.shared.u64 t, %1; cvt.u32.u64 %0, t; }" : "=r"(a) : "l"(p));
    return a;
}
#define SWZ128(o) ((o) ^ (((o) >> 3) & 0x70))

__device__ __forceinline__ void cp_async16(uint32_t s, const void* g) {
    asm volatile("cp.async.cg.shared.global [%0], [%1], 16;" :: "r"(s), "l"(g));
}
__device__ __forceinline__ void ldsm_x4(uint32_t* r, uint32_t addr) {
    asm volatile("ldmatrix.sync.aligned.m8n8.x4.shared.b16 {%0,%1,%2,%3}, [%4];"
                 : "=r"(r[0]), "=r"(r[1]), "=r"(r[2]), "=r"(r[3]) : "r"(addr));
}
__device__ __forceinline__ void mma16816(float* d, const uint32_t* a, const uint32_t* b) {
    asm volatile("mma.sync.aligned.m16n8k16.row.col.f32.f16.f16.f32 "
                 "{%0,%1,%2,%3}, {%4,%5,%6,%7}, {%8,%9}, {%0,%1,%2,%3};"
                 : "+f"(d[0]), "+f"(d[1]), "+f"(d[2]), "+f"(d[3])
                 : "r"(a[0]), "r"(a[1]), "r"(a[2]), "r"(a[3]), "r"(b[0]), "r"(b[1]));
}

// ---------------------------------------------------------------------------
// fp32 -> (hi, lo) fp16 split (for A operands: O(1) data, lo stays normal)
// ---------------------------------------------------------------------------
__global__ __launch_bounds__(256) void split2_kernel(const float* __restrict__ in,
                                                     __half* __restrict__ hi,
                                                     __half* __restrict__ lo, int n) {
    int i = (blockIdx.x * 256 + threadIdx.x) * 4;
    if (i >= n) return;
    float4 v = *(const float4*)(in + i);
    __half h0 = __float2half(v.x), h1 = __float2half(v.y);
    __half h2 = __float2half(v.z), h3 = __float2half(v.w);
    __half l0 = __float2half(v.x - __half2float(h0));
    __half l1 = __float2half(v.y - __half2float(h1));
    __half l2 = __float2half(v.z - __half2float(h2));
    __half l3 = __float2half(v.w - __half2float(h3));
    *(__half2*)(hi + i)     = __halves2half2(h0, h1);
    *(__half2*)(hi + i + 2) = __halves2half2(h2, h3);
    *(__half2*)(lo + i)     = __halves2half2(l0, l1);
    *(__half2*)(lo + i + 2) = __halves2half2(l2, l3);
}

// fp32 -> fp16 convert (weights; rounding error carried as the dropped term)
__global__ __launch_bounds__(256) void convert_kernel(const float* __restrict__ in,
                                                      __half* __restrict__ out, int n) {
    int i = (blockIdx.x * 256 + threadIdx.x) * 4;
    if (i >= n) return;
    float4 v = *(const float4*)(in + i);
    *(__half2*)(out + i)     = __halves2half2(__float2half(v.x), __float2half(v.y));
    *(__half2*)(out + i + 2) = __halves2half2(__float2half(v.z), __float2half(v.w));
}

// ---------------------------------------------------------------------------
// Tensor-core GEMM: C[M,N] = (Ah+Al)[M,K] * Bh[N,K]^T, K=1024, fp16 2-term,
// fp32 accum. CTA tile 128x128, K-chunk 64, 2-stage cp.async pipeline.
// 8 warps as 2(M) x 4(N), warp tile 64x32.
// smem: 2 stages x 3 tiles (Ah, Al, Bh) x 16 KB = 96 KB; 2 CTAs/SM.
// epi_mode 0: scatter into g_qkv; 1: plain fp32 write to Cout.
// ---------------------------------------------------------------------------
#define TILE_SZ   16384u
#define STAGE_SZ  49152u
#define GEMM_SMEM (2 * 49152)

__global__ __launch_bounds__(256, 2) void gemm_tc_kernel(
    const __half* __restrict__ Ahi, const __half* __restrict__ Alo,
    const __half* __restrict__ Bh,
    float* __restrict__ Cout, int epi_mode) {
    extern __shared__ char sm[];
    const uint32_t smb = smem_to_u32(sm);
    const int tid = threadIdx.x;
    const int wid = tid >> 5, lane = tid & 31;
    const int wm = wid & 1, wn = wid >> 1;
    const int m0 = blockIdx.y * 128, n0 = blockIdx.x * 128;

    float acc[4][4][4];
#pragma unroll
    for (int mi = 0; mi < 4; mi++)
#pragma unroll
        for (int ni = 0; ni < 4; ni++)
#pragma unroll
            for (int e = 0; e < 4; e++) acc[mi][ni][e] = 0.f;

    // per-thread fragment address components
    const int a_row = wm * 64 + (lane & 15);                      // + mi*16
    const int a_kb  = (lane >> 4) << 4;                           // + ks*32
    const int b_row = wn * 32 + ((lane >> 4) << 3) + (lane & 7);  // + p*16
    const int b_kb  = ((lane >> 3) & 1) << 4;                     // + ks*32

    // load-address components (12 cp.async per thread per chunk)
    const int l_row = tid >> 1;                  // + tt*... rows 0..127 over 2 sub
    // each tile: 1024 x 16B; thread does 4: w = tt*256 + tid
    auto load_chunk = [&](int c, int s) {
        const uint32_t sbase = smb + (uint32_t)s * STAGE_SZ;
#pragma unroll
        for (int tile = 0; tile < 3; tile++) {
            const __half* src = (tile == 0) ? Ahi : (tile == 1) ? Alo : Bh;
            const int rbase = (tile < 2) ? m0 : n0;
#pragma unroll
            for (int tt = 0; tt < 4; tt++) {
                int w = tt * 256 + tid;
                int row = w >> 3, g = (w & 7) << 4;
                const char* gp = (const char*)src
                               + ((size_t)(rbase + row) * KDIM + (size_t)c * 64) * 2 + g;
                uint32_t off = (uint32_t)(row * 128 + g);
                cp_async16(sbase + (uint32_t)tile * TILE_SZ + SWZ128(off), gp);
            }
        }
        asm volatile("cp.async.commit_group;" ::: "memory");
    };
    (void)l_row;

    load_chunk(0, 0);
    for (int c = 0; c < 16; c++) {
        if (c < 15) {
            load_chunk(c + 1, (c + 1) & 1);
            asm volatile("cp.async.wait_group 1;" ::: "memory");
        } else {
            asm volatile("cp.async.wait_group 0;" ::: "memory");
        }
        __syncthreads();

        const uint32_t sbase = smb + (uint32_t)(c & 1) * STAGE_SZ;
        const uint32_t tA_hi = sbase, tA_lo = sbase + TILE_SZ, tB = sbase + 2 * TILE_SZ;
#pragma unroll
        for (int ks = 0; ks < 4; ks++) {
            uint32_t af[4][4], bhf[2][4];
#pragma unroll
            for (int p = 0; p < 2; p++) {
                uint32_t off = (uint32_t)((b_row + p * 16) * 128 + ks * 32 + b_kb);
                ldsm_x4(bhf[p], tB + SWZ128(off));
            }
#pragma unroll
            for (int mi = 0; mi < 4; mi++) {
                uint32_t off = (uint32_t)((a_row + mi * 16) * 128 + ks * 32 + a_kb);
                ldsm_x4(af[mi], tA_hi + SWZ128(off));
            }
#pragma unroll
            for (int mi = 0; mi < 4; mi++)
#pragma unroll
                for (int ni = 0; ni < 4; ni++)
                    mma16816(acc[mi][ni], af[mi], &bhf[ni >> 1][(ni & 1) * 2]);   // hi*B
#pragma unroll
            for (int mi = 0; mi < 4; mi++) {   // reload A as lo (reuse regs)
                uint32_t off = (uint32_t)((a_row + mi * 16) * 128 + ks * 32 + a_kb);
                ldsm_x4(af[mi], tA_lo + SWZ128(off));
            }
#pragma unroll
            for (int mi = 0; mi < 4; mi++)
#pragma unroll
                for (int ni = 0; ni < 4; ni++)
                    mma16816(acc[mi][ni], af[mi], &bhf[ni >> 1][(ni & 1) * 2]);   // lo*B
        }
        __syncthreads();   // stage free before the load issued next iteration
    }

    // ---- epilogue ----
    const int ml = wm * 64 + (lane >> 2);
    const int nl = wn * 32 + ((lane & 3) << 1);
#pragma unroll
    for (int mi = 0; mi < 4; mi++)
#pragma unroll
        for (int ni = 0; ni < 4; ni++)
#pragma unroll
            for (int half = 0; half < 2; half++) {
                int row = m0 + ml + mi * 16 + half * 8;
                int col = n0 + nl + ni * 8;
                float2 v = make_float2(acc[mi][ni][half * 2], acc[mi][ni][half * 2 + 1]);
                if (epi_mode == 0) {
                    int which = col >> 10, hh = (col & 1023) >> 6, d0 = col & 63;
                    int bb = row >> 12, mm = row & 4095;
                    size_t base = ((((size_t)which * B_ + bb) * H_ + hh) * (size_t)M_ + mm)
                                  * HD_ + d0;
                    *(float2*)&g_qkv[base] = v;
                } else {
                    *(float2*)&Cout[(size_t)row * 1024 + col] = v;
                }
            }
}

// ---------------------------------------------------------------------------
// Attention: one CTA per (segment, head, batch). Faithful reference quirk.
// Emits fp16 hi/lo split directly for the output-projection GEMM.
// ---------------------------------------------------------------------------
__global__ __launch_bounds__(256) void hilbert_attn_kernel(const int* __restrict__ hmap) {
    extern __shared__ float smf[];
    float (*Qs)[65] = (float (*)[65])(smf);
    float (*Ks)[65] = (float (*)[65])(smf + 64 * 65);
    float (*Vs)[65] = (float (*)[65])(smf + 2 * 64 * 65);
    float (*Ss)[65] = (float (*)[65])(smf + 3 * 64 * 65);
    __shared__ float cmax[64];
    __shared__ float dsum[64];
    __shared__ int   kposs[64];

    int s = blockIdx.x, h = blockIdx.y, b = blockIdx.z;
    int tid = threadIdx.x;

    size_t qbase = (((size_t)0 * B_ + b) * H_ + h) * (size_t)M_ * HD_;
    size_t kbase = (((size_t)1 * B_ + b) * H_ + h) * (size_t)M_ * HD_;
    size_t vbase = (((size_t)2 * B_ + b) * H_ + h) * (size_t)M_ * HD_;

    if (tid < 64) kposs[tid] = hmap[s * SEG_ + tid * 2];
    __syncthreads();

    for (int idx = tid; idx < 64 * 64; idx += 256) {
        int r = idx >> 6, d = idx & 63;
        int p = kposs[r];
        Ks[r][d] = g_qkv[kbase + (size_t)p * HD_ + d];
        Vs[r][d] = g_qkv[vbase + (size_t)p * HD_ + d];
    }

    int q0 = (tid >> 4) << 2;
    int t0 = (tid & 15) << 2;

    for (int n = 0; n < 2; n++) {
        __syncthreads();
        for (int idx = tid; idx < 64 * 64; idx += 256) {
            int r = idx >> 6, d = idx & 63;
            int p = hmap[s * SEG_ + n * 64 + r];
            Qs[r][d] = g_qkv[qbase + (size_t)p * HD_ + d] * SCALE_;
        }
        __syncthreads();

        float acc[4][4];
#pragma unroll
        for (int i = 0; i < 4; i++)
#pragma unroll
            for (int j = 0; j < 4; j++) acc[i][j] = 0.f;
#pragma unroll 8
        for (int kk = 0; kk < 64; kk++) {
            float qa[4], kb[4];
#pragma unroll
            for (int i = 0; i < 4; i++) qa[i] = Qs[q0 + i][kk];
#pragma unroll
            for (int j = 0; j < 4; j++) kb[j] = Ks[t0 + j][kk];
#pragma unroll
            for (int i = 0; i < 4; i++)
#pragma unroll
                for (int j = 0; j < 4; j++) acc[i][j] += qa[i] * kb[j];
        }
#pragma unroll
        for (int i = 0; i < 4; i++)
#pragma unroll
            for (int j = 0; j < 4; j++) Ss[q0 + i][t0 + j] = acc[i][j];
        __syncthreads();

        if (tid < 64) {
            float mx = -1e30f;
#pragma unroll 8
            for (int q = 0; q < 64; q++) mx = fmaxf(mx, Ss[q][tid]);
            cmax[tid] = mx;
        }
        __syncthreads();

#pragma unroll
        for (int i = 0; i < 4; i++)
#pragma unroll
            for (int j = 0; j < 4; j++)
                Ss[q0 + i][t0 + j] = __expf(acc[i][j] - cmax[t0 + j]);
        __syncthreads();

        if (tid < 64) {
            float sum = 1e-10f;
#pragma unroll 8
            for (int t = 0; t < 64; t++) sum += Ss[tid][t];
            dsum[tid] = sum;
        }
        __syncthreads();

        float oac[4][4];
#pragma unroll
        for (int i = 0; i < 4; i++)
#pragma unroll
            for (int j = 0; j < 4; j++) oac[i][j] = 0.f;
#pragma unroll 8
        for (int t = 0; t < 64; t++) {
            float wa[4], vb[4];
#pragma unroll
            for (int i = 0; i < 4; i++) wa[i] = Ss[q0 + i][t];
#pragma unroll
            for (int j = 0; j < 4; j++) vb[j] = Vs[t][t0 + j];
#pragma unroll
            for (int i = 0; i < 4; i++)
#pragma unroll
                for (int j = 0; j < 4; j++) oac[i][j] += wa[i] * vb[j];
        }
#pragma unroll
        for (int i = 0; i < 4; i++) {
            int q = q0 + i;
            float inv = 1.0f / dsum[q];
            int m = s * SEG_ + n * 64 + q;
            size_t o = ((size_t)(b * M_ + m)) * DM_ + h * HD_ + t0;
#pragma unroll
            for (int j = 0; j < 4; j++) {
                float v = oac[i][j] * inv;
                __half hv = __float2half(v);
                g_att_hi[o + j] = hv;
                g_att_lo[o + j] = __float2half(v - __half2float(hv));
            }
        }
    }
}

// ---------------------------------------------------------------------------

extern "C" void kernel_launch(void* const* d_in, const int* in_sizes, int n_in,
                              void* d_out, int out_size) {
    const float* x    = (const float*)d_in[0];
    const float* Wqkv = (const float*)d_in[1];
    const float* Wout = (const float*)d_in[2];
    const int*   hmap = (const int*)d_in[3];
    float* out = (float*)d_out;
    (void)in_sizes; (void)n_in; (void)out_size;

    __half *xh, *xl, *qh, *oh, *ah, *al;
    cudaGetSymbolAddress((void**)&xh, g_x_hi);   cudaGetSymbolAddress((void**)&xl, g_x_lo);
    cudaGetSymbolAddress((void**)&qh, g_wqkv_h); cudaGetSymbolAddress((void**)&oh, g_wout_h);
    cudaGetSymbolAddress((void**)&ah, g_att_hi); cudaGetSymbolAddress((void**)&al, g_att_lo);

    // 0) fp16 conversions: x split (hi+lo), weights plain
    split2_kernel<<<(B_ * M_ * DM_) / 1024, 256>>>(x, xh, xl, B_ * M_ * DM_);
    convert_kernel<<<(3 * DM_ * DM_) / 1024, 256>>>(Wqkv, qh, 3 * DM_ * DM_);
    convert_kernel<<<(DM_ * DM_) / 1024, 256>>>(Wout, oh, DM_ * DM_);

    cudaFuncSetAttribute((const void*)gemm_tc_kernel,
                         cudaFuncAttributeMaxDynamicSharedMemorySize, GEMM_SMEM);

    // 1) QKV projection: [16384,1024] x [3072,1024]^T -> g_qkv (scatter)
    gemm_tc_kernel<<<dim3(24, 128), 256, GEMM_SMEM>>>(xh, xl, qh, nullptr, 0);

    // 2) Hilbert segmented attention (writes fp16 hi/lo)
    const int smem = 4 * 64 * 65 * (int)sizeof(float);
    cudaFuncSetAttribute((const void*)hilbert_attn_kernel,
                         cudaFuncAttributeMaxDynamicSharedMemorySize, smem);
    hilbert_attn_kernel<<<dim3(NSEG_, H_, B_), 256, smem>>>(hmap);

    // 3) Output projection: [16384,1024] x [1024,1024]^T -> out
    gemm_tc_kernel<<<dim3(8, 128), 256, GEMM_SMEM>>>(ah, al, oh, out, 1);
}

// round 8
// speedup vs baseline: 4.7527x; 1.2194x over previous
#include <cuda_runtime.h>
#include <cuda_fp16.h>
#include <cstdint>

// Problem constants
#define B_    4
#define M_    4096
#define DM_   1024
#define H_    16
#define HD_   64
#define SEG_  128
#define NSEG_ 32
#define TKV_  64            // dilated keys per segment
#define KVROWS (NSEG_ * TKV_)   // 2048 kv positions per batch
#define SCALE_ 0.125f
#define KDIM  1024

// ---------------------------------------------------------------------------
// Scratch (device globals: allocation-free per harness rules)
// ---------------------------------------------------------------------------
__device__ float g_q[(size_t)B_ * H_ * M_ * HD_];                 // scaled, hmap-ordered
__device__ float g_kv[(size_t)2 * B_ * H_ * KVROWS * HD_];        // [k/v][b][h][s*64+t][d]
__device__ __half g_x_hi[(size_t)B_ * M_ * DM_];
__device__ __half g_x_lo[(size_t)B_ * M_ * DM_];
__device__ __half g_wqkv_h[3 * DM_ * DM_];
__device__ __half g_wout_h[DM_ * DM_];
__device__ __half g_att_hi[(size_t)B_ * M_ * DM_];
__device__ __half g_att_lo[(size_t)B_ * M_ * DM_];

// ---------------------------------------------------------------------------
// Helpers (compute_103-safe: no tcgen05/TMEM — those are sm_103a-gated PTX)
// ---------------------------------------------------------------------------
__device__ __forceinline__ uint32_t smem_to_u32(const void* p) {
    uint32_t a;
    asm("{ .reg .u64 t; cvta.to.shared.u64 t, %1; cvt.u32.u64 %0, t; }" : "=r"(a) : "l"(p));
    return a;
}
#define SWZ128(o) ((o) ^ (((o) >> 3) & 0x70))

__device__ __forceinline__ void cp_async16(uint32_t s, const void* g) {
    asm volatile("cp.async.cg.shared.global [%0], [%1], 16;" :: "r"(s), "l"(g));
}
__device__ __forceinline__ void ldsm_x4(uint32_t* r, uint32_t addr) {
    asm volatile("ldmatrix.sync.aligned.m8n8.x4.shared.b16 {%0,%1,%2,%3}, [%4];"
                 : "=r"(r[0]), "=r"(r[1]), "=r"(r[2]), "=r"(r[3]) : "r"(addr));
}
__device__ __forceinline__ void mma16816(float* d, const uint32_t* a, const uint32_t* b) {
    asm volatile("mma.sync.aligned.m16n8k16.row.col.f32.f16.f16.f32 "
                 "{%0,%1,%2,%3}, {%4,%5,%6,%7}, {%8,%9}, {%0,%1,%2,%3};"
                 : "+f"(d[0]), "+f"(d[1]), "+f"(d[2]), "+f"(d[3])
                 : "r"(a[0]), "r"(a[1]), "r"(a[2]), "r"(a[3]), "r"(b[0]), "r"(b[1]));
}

// ---------------------------------------------------------------------------
// fp32 -> (hi, lo) fp16 split (A operands: O(1) data, lo stays normal)
// ---------------------------------------------------------------------------
__global__ __launch_bounds__(256) void split2_kernel(const float* __restrict__ in,
                                                     __half* __restrict__ hi,
                                                     __half* __restrict__ lo, int n) {
    int i = (blockIdx.x * 256 + threadIdx.x) * 4;
    if (i >= n) return;
    float4 v = *(const float4*)(in + i);
    __half h0 = __float2half(v.x), h1 = __float2half(v.y);
    __half h2 = __float2half(v.z), h3 = __float2half(v.w);
    __half l0 = __float2half(v.x - __half2float(h0));
    __half l1 = __float2half(v.y - __half2float(h1));
    __half l2 = __float2half(v.z - __half2float(h2));
    __half l3 = __float2half(v.w - __half2float(h3));
    *(__half2*)(hi + i)     = __halves2half2(h0, h1);
    *(__half2*)(hi + i + 2) = __halves2half2(h2, h3);
    *(__half2*)(lo + i)     = __halves2half2(l0, l1);
    *(__half2*)(lo + i + 2) = __halves2half2(l2, l3);
}

__global__ __launch_bounds__(256) void convert_kernel(const float* __restrict__ in,
                                                      __half* __restrict__ out, int n) {
    int i = (blockIdx.x * 256 + threadIdx.x) * 4;
    if (i >= n) return;
    float4 v = *(const float4*)(in + i);
    *(__half2*)(out + i)     = __halves2half2(__float2half(v.x), __float2half(v.y));
    *(__half2*)(out + i + 2) = __halves2half2(__float2half(v.z), __float2half(v.w));
}

// ---------------------------------------------------------------------------
// Tensor-core GEMM: C = (Ah+Al)[rows gathered] * Bh[N,K]^T, K=1024, fp16
// 2-term split, fp32 accum. CTA tile 128x128, K-chunk 64, 2-stage cp.async.
// 8 warps as 2(M) x 4(N), warp tile 64x32. smem 96 KB; 2 CTAs/SM.
// epi_mode: 0 = Q (gather hmap rows, scale, write g_q)
//           1 = KV (gather dilated hmap rows, write g_kv)
//           2 = OUT (identity rows, plain fp32 write to Cout)
// ---------------------------------------------------------------------------
#define TILE_SZ   16384u
#define STAGE_SZ  49152u
#define GEMM_SMEM (2 * 49152)

__global__ __launch_bounds__(256, 2) void gemm_tc_kernel(
    const __half* __restrict__ Ahi, const __half* __restrict__ Alo,
    const __half* __restrict__ Bh,
    float* __restrict__ Cout, int epi_mode, const int* __restrict__ hmap) {
    extern __shared__ char sm[];
    __shared__ int rowmap[128];
    const uint32_t smb = smem_to_u32(sm);
    const int tid = threadIdx.x;
    const int wid = tid >> 5, lane = tid & 31;
    const int wm = wid & 1, wn = wid >> 1;
    const int m0 = blockIdx.y * 128, n0 = blockIdx.x * 128;

    // ---- per-CTA A-row gather map (global x/att row per tile row) ----
    if (tid < 128) {
        int r;
        if (epi_mode == 0) {            // Q: row (b, mq) reads x[b, hmap[mq]]
            int bb = m0 >> 12, mq = (m0 & 4095) + tid;
            r = bb * M_ + hmap[mq];
        } else if (epi_mode == 1) {     // KV: row (b, rr) reads x[b, hmap[s*128+t*2]]
            int bb = m0 >> 11, rr = (m0 & 2047) + tid;
            int s = rr >> 6, t = rr & 63;
            r = bb * M_ + hmap[s * SEG_ + t * 2];
        } else {
            r = m0 + tid;
        }
        rowmap[tid] = r;
    }
    __syncthreads();

    float acc[4][4][4];
#pragma unroll
    for (int mi = 0; mi < 4; mi++)
#pragma unroll
        for (int ni = 0; ni < 4; ni++)
#pragma unroll
            for (int e = 0; e < 4; e++) acc[mi][ni][e] = 0.f;

    const int a_row = wm * 64 + (lane & 15);
    const int a_kb  = (lane >> 4) << 4;
    const int b_row = wn * 32 + ((lane >> 4) << 3) + (lane & 7);
    const int b_kb  = ((lane >> 3) & 1) << 4;

    auto load_chunk = [&](int c, int s) {
        const uint32_t sbase = smb + (uint32_t)s * STAGE_SZ;
#pragma unroll
        for (int tile = 0; tile < 3; tile++) {
            const __half* src = (tile == 0) ? Ahi : (tile == 1) ? Alo : Bh;
#pragma unroll
            for (int tt = 0; tt < 4; tt++) {
                int w = tt * 256 + tid;
                int row = w >> 3, g = (w & 7) << 4;
                int grow = (tile < 2) ? rowmap[row] : (n0 + row);
                const char* gp = (const char*)src
                               + ((size_t)grow * KDIM + (size_t)c * 64) * 2 + g;
                uint32_t off = (uint32_t)(row * 128 + g);
                cp_async16(sbase + (uint32_t)tile * TILE_SZ + SWZ128(off), gp);
            }
        }
        asm volatile("cp.async.commit_group;" ::: "memory");
    };

    load_chunk(0, 0);
    for (int c = 0; c < 16; c++) {
        if (c < 15) {
            load_chunk(c + 1, (c + 1) & 1);
            asm volatile("cp.async.wait_group 1;" ::: "memory");
        } else {
            asm volatile("cp.async.wait_group 0;" ::: "memory");
        }
        __syncthreads();

        const uint32_t sbase = smb + (uint32_t)(c & 1) * STAGE_SZ;
        const uint32_t tA_hi = sbase, tA_lo = sbase + TILE_SZ, tB = sbase + 2 * TILE_SZ;
#pragma unroll
        for (int ks = 0; ks < 4; ks++) {
            uint32_t af[4][4], bhf[2][4];
#pragma unroll
            for (int p = 0; p < 2; p++) {
                uint32_t off = (uint32_t)((b_row + p * 16) * 128 + ks * 32 + b_kb);
                ldsm_x4(bhf[p], tB + SWZ128(off));
            }
#pragma unroll
            for (int mi = 0; mi < 4; mi++) {
                uint32_t off = (uint32_t)((a_row + mi * 16) * 128 + ks * 32 + a_kb);
                ldsm_x4(af[mi], tA_hi + SWZ128(off));
            }
#pragma unroll
            for (int mi = 0; mi < 4; mi++)
#pragma unroll
                for (int ni = 0; ni < 4; ni++)
                    mma16816(acc[mi][ni], af[mi], &bhf[ni >> 1][(ni & 1) * 2]);   // hi*B
#pragma unroll
            for (int mi = 0; mi < 4; mi++) {
                uint32_t off = (uint32_t)((a_row + mi * 16) * 128 + ks * 32 + a_kb);
                ldsm_x4(af[mi], tA_lo + SWZ128(off));
            }
#pragma unroll
            for (int mi = 0; mi < 4; mi++)
#pragma unroll
                for (int ni = 0; ni < 4; ni++)
                    mma16816(acc[mi][ni], af[mi], &bhf[ni >> 1][(ni & 1) * 2]);   // lo*B
        }
        __syncthreads();
    }

    // ---- epilogue ----
    const int ml = wm * 64 + (lane >> 2);
    const int nl = wn * 32 + ((lane & 3) << 1);
#pragma unroll
    for (int mi = 0; mi < 4; mi++)
#pragma unroll
        for (int ni = 0; ni < 4; ni++)
#pragma unroll
            for (int half = 0; half < 2; half++) {
                int row = m0 + ml + mi * 16 + half * 8;
                int col = n0 + nl + ni * 8;
                float2 v = make_float2(acc[mi][ni][half * 2], acc[mi][ni][half * 2 + 1]);
                if (epi_mode == 0) {
                    // q: scaled, stored hmap-ordered [b][h][mq][d]
                    int hh = col >> 6, d0 = col & 63;
                    int bb = row >> 12, mq = row & 4095;
                    size_t base = (((size_t)bb * H_ + hh) * (size_t)M_ + mq) * HD_ + d0;
                    g_q[base]     = v.x * SCALE_;
                    g_q[base + 1] = v.y * SCALE_;
                } else if (epi_mode == 1) {
                    // k/v: [which][b][h][s*64+t][d]
                    int which = col >> 10, hh = (col & 1023) >> 6, d0 = col & 63;
                    int bb = row >> 11, rr = row & 2047;
                    size_t base = ((((size_t)which * B_ + bb) * H_ + hh) * KVROWS + rr)
                                  * HD_ + d0;
                    *(float2*)&g_kv[base] = v;
                } else {
                    *(float2*)&Cout[(size_t)row * 1024 + col] = v;
                }
            }
}

// ---------------------------------------------------------------------------
// Attention: one CTA per (segment, head, batch). All loads contiguous now
// (gathers + scale were absorbed into the GEMM epilogues/loaders).
// Faithful reference quirk: per-KEY max over 64-query block, unrescaled exp.
// Emits fp16 hi/lo split for the output-projection GEMM.
// ---------------------------------------------------------------------------
__global__ __launch_bounds__(256) void hilbert_attn_kernel() {
    extern __shared__ float smf[];
    float (*Qs)[65] = (float (*)[65])(smf);
    float (*Ks)[65] = (float (*)[65])(smf + 64 * 65);
    float (*Vs)[65] = (float (*)[65])(smf + 2 * 64 * 65);
    float (*Ss)[65] = (float (*)[65])(smf + 3 * 64 * 65);
    __shared__ float cmax[64];
    __shared__ float dsum[64];

    int s = blockIdx.x, h = blockIdx.y, b = blockIdx.z;
    int tid = threadIdx.x;

    size_t qbase = (((size_t)b * H_ + h) * (size_t)M_ + (size_t)s * SEG_) * HD_;
    size_t kbase = ((((size_t)0 * B_ + b) * H_ + h) * KVROWS + (size_t)s * TKV_) * HD_;
    size_t vbase = ((((size_t)1 * B_ + b) * H_ + h) * KVROWS + (size_t)s * TKV_) * HD_;

    for (int idx = tid; idx < 64 * 16; idx += 256) {    // float4 granularity
        int r = idx >> 4, d4 = (idx & 15) << 2;
        float4 kv4 = *(const float4*)&g_kv[kbase + (size_t)r * HD_ + d4];
        Ks[r][d4] = kv4.x; Ks[r][d4 + 1] = kv4.y; Ks[r][d4 + 2] = kv4.z; Ks[r][d4 + 3] = kv4.w;
        float4 vv4 = *(const float4*)&g_kv[vbase + (size_t)r * HD_ + d4];
        Vs[r][d4] = vv4.x; Vs[r][d4 + 1] = vv4.y; Vs[r][d4 + 2] = vv4.z; Vs[r][d4 + 3] = vv4.w;
    }

    int q0 = (tid >> 4) << 2;
    int t0 = (tid & 15) << 2;

    for (int n = 0; n < 2; n++) {
        __syncthreads();
        for (int idx = tid; idx < 64 * 16; idx += 256) {
            int r = idx >> 4, d4 = (idx & 15) << 2;
            float4 q4 = *(const float4*)&g_q[qbase + (size_t)(n * 64 + r) * HD_ + d4];
            Qs[r][d4] = q4.x; Qs[r][d4 + 1] = q4.y; Qs[r][d4 + 2] = q4.z; Qs[r][d4 + 3] = q4.w;
        }
        __syncthreads();

        float acc[4][4];
#pragma unroll
        for (int i = 0; i < 4; i++)
#pragma unroll
            for (int j = 0; j < 4; j++) acc[i][j] = 0.f;
#pragma unroll 8
        for (int kk = 0; kk < 64; kk++) {
            float qa[4], kb[4];
#pragma unroll
            for (int i = 0; i < 4; i++) qa[i] = Qs[q0 + i][kk];
#pragma unroll
            for (int j = 0; j < 4; j++) kb[j] = Ks[t0 + j][kk];
#pragma unroll
            for (int i = 0; i < 4; i++)
#pragma unroll
                for (int j = 0; j < 4; j++) acc[i][j] += qa[i] * kb[j];
        }
#pragma unroll
        for (int i = 0; i < 4; i++)
#pragma unroll
            for (int j = 0; j < 4; j++) Ss[q0 + i][t0 + j] = acc[i][j];
        __syncthreads();

        if (tid < 64) {
            float mx = -1e30f;
#pragma unroll 8
            for (int q = 0; q < 64; q++) mx = fmaxf(mx, Ss[q][tid]);
            cmax[tid] = mx;
        }
        __syncthreads();

#pragma unroll
        for (int i = 0; i < 4; i++)
#pragma unroll
            for (int j = 0; j < 4; j++)
                Ss[q0 + i][t0 + j] = __expf(acc[i][j] - cmax[t0 + j]);
        __syncthreads();

        if (tid < 64) {
            float sum = 1e-10f;
#pragma unroll 8
            for (int t = 0; t < 64; t++) sum += Ss[tid][t];
            dsum[tid] = sum;
        }
        __syncthreads();

        float oac[4][4];
#pragma unroll
        for (int i = 0; i < 4; i++)
#pragma unroll
            for (int j = 0; j < 4; j++) oac[i][j] = 0.f;
#pragma unroll 8
        for (int t = 0; t < 64; t++) {
            float wa[4], vb[4];
#pragma unroll
            for (int i = 0; i < 4; i++) wa[i] = Ss[q0 + i][t];
#pragma unroll
            for (int j = 0; j < 4; j++) vb[j] = Vs[t][t0 + j];
#pragma unroll
            for (int i = 0; i < 4; i++)
#pragma unroll
                for (int j = 0; j < 4; j++) oac[i][j] += wa[i] * vb[j];
        }
#pragma unroll
        for (int i = 0; i < 4; i++) {
            int q = q0 + i;
            float inv = 1.0f / dsum[q];
            int m = s * SEG_ + n * 64 + q;
            size_t o = ((size_t)(b * M_ + m)) * DM_ + h * HD_ + t0;
#pragma unroll
            for (int j = 0; j < 4; j++) {
                float v = oac[i][j] * inv;
                __half hv = __float2half(v);
                g_att_hi[o + j] = hv;
                g_att_lo[o + j] = __float2half(v - __half2float(hv));
            }
        }
    }
}

// ---------------------------------------------------------------------------

extern "C" void kernel_launch(void* const* d_in, const int* in_sizes, int n_in,
                              void* d_out, int out_size) {
    const float* x    = (const float*)d_in[0];
    const float* Wqkv = (const float*)d_in[1];
    const float* Wout = (const float*)d_in[2];
    const int*   hmap = (const int*)d_in[3];
    float* out = (float*)d_out;
    (void)in_sizes; (void)n_in; (void)out_size;

    __half *xh, *xl, *qh, *oh, *ah, *al;
    cudaGetSymbolAddress((void**)&xh, g_x_hi);   cudaGetSymbolAddress((void**)&xl, g_x_lo);
    cudaGetSymbolAddress((void**)&qh, g_wqkv_h); cudaGetSymbolAddress((void**)&oh, g_wout_h);
    cudaGetSymbolAddress((void**)&ah, g_att_hi); cudaGetSymbolAddress((void**)&al, g_att_lo);

    // 0) fp16 conversions: x split (hi+lo), weights plain
    split2_kernel<<<(B_ * M_ * DM_) / 1024, 256>>>(x, xh, xl, B_ * M_ * DM_);
    convert_kernel<<<(3 * DM_ * DM_) / 1024, 256>>>(Wqkv, qh, 3 * DM_ * DM_);
    convert_kernel<<<(DM_ * DM_) / 1024, 256>>>(Wout, oh, DM_ * DM_);

    cudaFuncSetAttribute((const void*)gemm_tc_kernel,
                         cudaFuncAttributeMaxDynamicSharedMemorySize, GEMM_SMEM);

    // 1) Q projection (gathered rows, scaled): [16384,1024] x Wq[1024,1024]^T
    gemm_tc_kernel<<<dim3(8, 128), 256, GEMM_SMEM>>>(xh, xl, qh, nullptr, 0, hmap);

    // 2) KV projection (dilated rows only): [8192,1024] x Wkv[2048,1024]^T
    gemm_tc_kernel<<<dim3(16, 64), 256, GEMM_SMEM>>>(xh, xl, qh + 1024 * 1024,
                                                     nullptr, 1, hmap);

    // 3) Hilbert segmented attention (all-contiguous; writes fp16 hi/lo)
    const int smem = 4 * 64 * 65 * (int)sizeof(float);
    cudaFuncSetAttribute((const void*)hilbert_attn_kernel,
                         cudaFuncAttributeMaxDynamicSharedMemorySize, smem);
    hilbert_attn_kernel<<<dim3(NSEG_, H_, B_), 256, smem>>>();

    // 4) Output projection: [16384,1024] x [1024,1024]^T -> out
    gemm_tc_kernel<<<dim3(8, 128), 256, GEMM_SMEM>>>(ah, al, oh, out, 2, hmap);
}

// round 10
// speedup vs baseline: 5.0858x; 1.0701x over previous
#include <cuda_runtime.h>
#include <cuda_fp16.h>
#include <cstdint>

// Problem constants
#define B_    4
#define M_    4096
#define DM_   1024
#define H_    16
#define HD_   64
#define SEG_  128
#define NSEG_ 32
#define TKV_  64
#define KVROWS (NSEG_ * TKV_)
#define SCALE_ 0.125f
#define KDIM  1024

// ---------------------------------------------------------------------------
// Scratch (device globals: allocation-free per harness rules)
// ---------------------------------------------------------------------------
__device__ float g_q[(size_t)B_ * H_ * M_ * HD_];
__device__ float g_kv[(size_t)2 * B_ * H_ * KVROWS * HD_];
__device__ __half g_x_hi[(size_t)B_ * M_ * DM_];
__device__ __half g_x_lo[(size_t)B_ * M_ * DM_];
__device__ __half g_wqkv_h[3 * DM_ * DM_];
__device__ __half g_wout_h[DM_ * DM_];
__device__ __half g_att_hi[(size_t)B_ * M_ * DM_];
__device__ __half g_att_lo[(size_t)B_ * M_ * DM_];

// ---------------------------------------------------------------------------
// Helpers (compute_103-safe)
// ---------------------------------------------------------------------------
__device__ __forceinline__ uint32_t smem_to_u32(const void* p) {
    uint32_t a;
    asm("{ .reg .u64 t; cvta.to.shared.u64 t, %1; cvt.u32.u64 %0, t; }" : "=r"(a) : "l"(p));
    return a;
}
#define SWZ128(o) ((o) ^ (((o) >> 3) & 0x70))

__device__ __forceinline__ void cp_async16(uint32_t s, const void* g) {
    asm volatile("cp.async.cg.shared.global [%0], [%1], 16;" :: "r"(s), "l"(g));
}
__device__ __forceinline__ void ldsm_x4(uint32_t* r, uint32_t addr) {
    asm volatile("ldmatrix.sync.aligned.m8n8.x4.shared.b16 {%0,%1,%2,%3}, [%4];"
                 : "=r"(r[0]), "=r"(r[1]), "=r"(r[2]), "=r"(r[3]) : "r"(addr));
}
__device__ __forceinline__ void mma16816(float* d, const uint32_t* a, const uint32_t* b) {
    asm volatile("mma.sync.aligned.m16n8k16.row.col.f32.f16.f16.f32 "
                 "{%0,%1,%2,%3}, {%4,%5,%6,%7}, {%8,%9}, {%0,%1,%2,%3};"
                 : "+f"(d[0]), "+f"(d[1]), "+f"(d[2]), "+f"(d[3])
                 : "r"(a[0]), "r"(a[1]), "r"(a[2]), "r"(a[3]), "r"(b[0]), "r"(b[1]));
}

// ---------------------------------------------------------------------------
// fp32 -> fp16 split / convert
// ---------------------------------------------------------------------------
__global__ __launch_bounds__(256) void split2_kernel(const float* __restrict__ in,
                                                     __half* __restrict__ hi,
                                                     __half* __restrict__ lo, int n) {
    int i = (blockIdx.x * 256 + threadIdx.x) * 4;
    if (i >= n) return;
    float4 v = *(const float4*)(in + i);
    __half h0 = __float2half(v.x), h1 = __float2half(v.y);
    __half h2 = __float2half(v.z), h3 = __float2half(v.w);
    __half l0 = __float2half(v.x - __half2float(h0));
    __half l1 = __float2half(v.y - __half2float(h1));
    __half l2 = __float2half(v.z - __half2float(h2));
    __half l3 = __float2half(v.w - __half2float(h3));
    *(__half2*)(hi + i)     = __halves2half2(h0, h1);
    *(__half2*)(hi + i + 2) = __halves2half2(h2, h3);
    *(__half2*)(lo + i)     = __halves2half2(l0, l1);
    *(__half2*)(lo + i + 2) = __halves2half2(l2, l3);
}

__global__ __launch_bounds__(256) void convert_kernel(const float* __restrict__ in,
                                                      __half* __restrict__ out, int n) {
    int i = (blockIdx.x * 256 + threadIdx.x) * 4;
    if (i >= n) return;
    float4 v = *(const float4*)(in + i);
    *(__half2*)(out + i)     = __halves2half2(__float2half(v.x), __float2half(v.y));
    *(__half2*)(out + i + 2) = __halves2half2(__float2half(v.z), __float2half(v.w));
}

// ---------------------------------------------------------------------------
// Tensor-core GEMM, fp16 2-term split, fp32 accum. CTA tile 128x128,
// K-chunk 64, 2-stage cp.async. 8 warps 2(M)x4(N).
// qkv_mode: one merged launch covers Q (blocks 0..1023) and KV (1024..2047).
// out_mode: separate launch (epi 2).
// ---------------------------------------------------------------------------
#define TILE_SZ   16384u
#define STAGE_SZ  49152u
#define GEMM_SMEM (2 * 49152)

__global__ __launch_bounds__(256, 2) void gemm_tc_kernel(
    const __half* __restrict__ Ahi, const __half* __restrict__ Alo,
    const __half* __restrict__ Bq,  const __half* __restrict__ Bkv,
    float* __restrict__ Cout, int launch_mode, const int* __restrict__ hmap) {
    extern __shared__ char sm[];
    __shared__ int rowmap[128];
    const uint32_t smb = smem_to_u32(sm);
    const int tid = threadIdx.x;
    const int wid = tid >> 5, lane = tid & 31;
    const int wm = wid & 1, wn = wid >> 1;

    // ---- block -> (epi_mode, m0, n0, B) decode ----
    int epi_mode, m0, n0;
    const __half* Bh;
    if (launch_mode == 0) {           // merged Q + KV
        int bid = blockIdx.x;
        if (bid < 1024) { epi_mode = 0; m0 = (bid >> 3) * 128; n0 = (bid & 7) * 128; Bh = Bq; }
        else { bid -= 1024; epi_mode = 1; m0 = (bid >> 4) * 128; n0 = (bid & 15) * 128; Bh = Bkv; }
    } else {                          // out projection
        epi_mode = 2; m0 = (int)(blockIdx.x >> 3) * 128; n0 = (int)(blockIdx.x & 7) * 128;
        Bh = Bq;
    }

    if (tid < 128) {
        int r;
        if (epi_mode == 0) {          // Q: row (b, mq) reads x[b, hmap[mq]]
            int bb = m0 >> 12, mq = (m0 & 4095) + tid;
            r = bb * M_ + hmap[mq];
        } else if (epi_mode == 1) {   // KV: row (b, rr) reads x[b, hmap[s*128+t*2]]
            int bb = m0 >> 11, rr = (m0 & 2047) + tid;
            int s = rr >> 6, t = rr & 63;
            r = bb * M_ + hmap[s * SEG_ + t * 2];
        } else {
            r = m0 + tid;
        }
        rowmap[tid] = r;
    }
    __syncthreads();

    float acc[4][4][4];
#pragma unroll
    for (int mi = 0; mi < 4; mi++)
#pragma unroll
        for (int ni = 0; ni < 4; ni++)
#pragma unroll
            for (int e = 0; e < 4; e++) acc[mi][ni][e] = 0.f;

    const int a_row = wm * 64 + (lane & 15);
    const int a_kb  = (lane >> 4) << 4;
    const int b_row = wn * 32 + ((lane >> 4) << 3) + (lane & 7);
    const int b_kb  = ((lane >> 3) & 1) << 4;

    auto load_chunk = [&](int c, int s) {
        const uint32_t sbase = smb + (uint32_t)s * STAGE_SZ;
#pragma unroll
        for (int tile = 0; tile < 3; tile++) {
            const __half* src = (tile == 0) ? Ahi : (tile == 1) ? Alo : Bh;
#pragma unroll
            for (int tt = 0; tt < 4; tt++) {
                int w = tt * 256 + tid;
                int row = w >> 3, g = (w & 7) << 4;
                int grow = (tile < 2) ? rowmap[row] : (n0 + row);
                const char* gp = (const char*)src
                               + ((size_t)grow * KDIM + (size_t)c * 64) * 2 + g;
                uint32_t off = (uint32_t)(row * 128 + g);
                cp_async16(sbase + (uint32_t)tile * TILE_SZ + SWZ128(off), gp);
            }
        }
        asm volatile("cp.async.commit_group;" ::: "memory");
    };

    load_chunk(0, 0);
    for (int c = 0; c < 16; c++) {
        if (c < 15) {
            load_chunk(c + 1, (c + 1) & 1);
            asm volatile("cp.async.wait_group 1;" ::: "memory");
        } else {
            asm volatile("cp.async.wait_group 0;" ::: "memory");
        }
        __syncthreads();

        const uint32_t sbase = smb + (uint32_t)(c & 1) * STAGE_SZ;
        const uint32_t tA_hi = sbase, tA_lo = sbase + TILE_SZ, tB = sbase + 2 * TILE_SZ;
#pragma unroll
        for (int ks = 0; ks < 4; ks++) {
            uint32_t bhf[2][4];
#pragma unroll
            for (int p = 0; p < 2; p++) {
                uint32_t off = (uint32_t)((b_row + p * 16) * 128 + ks * 32 + b_kb);
                ldsm_x4(bhf[p], tB + SWZ128(off));
            }
            // interleaved hi/lo per mi: ldsm of mi+1 overlaps MMAs of mi
#pragma unroll
            for (int mi = 0; mi < 4; mi++) {
                uint32_t afh[4], afl[4];
                uint32_t off = (uint32_t)((a_row + mi * 16) * 128 + ks * 32 + a_kb);
                ldsm_x4(afh, tA_hi + SWZ128(off));
                ldsm_x4(afl, tA_lo + SWZ128(off));
#pragma unroll
                for (int ni = 0; ni < 4; ni++)
                    mma16816(acc[mi][ni], afh, &bhf[ni >> 1][(ni & 1) * 2]);
#pragma unroll
                for (int ni = 0; ni < 4; ni++)
                    mma16816(acc[mi][ni], afl, &bhf[ni >> 1][(ni & 1) * 2]);
            }
        }
        __syncthreads();
    }

    // ---- epilogue ----
    const int ml = wm * 64 + (lane >> 2);
    const int nl = wn * 32 + ((lane & 3) << 1);
#pragma unroll
    for (int mi = 0; mi < 4; mi++)
#pragma unroll
        for (int ni = 0; ni < 4; ni++)
#pragma unroll
            for (int half = 0; half < 2; half++) {
                int row = m0 + ml + mi * 16 + half * 8;
                int col = n0 + nl + ni * 8;
                float2 v = make_float2(acc[mi][ni][half * 2], acc[mi][ni][half * 2 + 1]);
                if (epi_mode == 0) {
                    int hh = col >> 6, d0 = col & 63;
                    int bb = row >> 12, mq = row & 4095;
                    size_t base = (((size_t)bb * H_ + hh) * (size_t)M_ + mq) * HD_ + d0;
                    g_q[base]     = v.x * SCALE_;
                    g_q[base + 1] = v.y * SCALE_;
                } else if (epi_mode == 1) {
                    int which = col >> 10, hh = (col & 1023) >> 6, d0 = col & 63;
                    int bb = row >> 11, rr = row & 2047;
                    size_t base = ((((size_t)which * B_ + bb) * H_ + hh) * KVROWS + rr)
                                  * HD_ + d0;
                    *(float2*)&g_kv[base] = v;
                } else {
                    *(float2*)&Cout[(size_t)row * 1024 + col] = v;
                }
            }
}

// ---------------------------------------------------------------------------
// Attention: one CTA per (segment, head, batch). Contiguous loads, parallel
// reductions (all 256 threads). Faithful reference quirk preserved.
// ---------------------------------------------------------------------------
__global__ __launch_bounds__(256) void hilbert_attn_kernel() {
    extern __shared__ float smf[];
    float (*Qs)[65] = (float (*)[65])(smf);
    float (*Ks)[65] = (float (*)[65])(smf + 64 * 65);
    float (*Vs)[65] = (float (*)[65])(smf + 2 * 64 * 65);
    float (*Ss)[65] = (float (*)[65])(smf + 3 * 64 * 65);
    __shared__ float part[4][64];
    __shared__ float cmax[64];
    __shared__ float dsum[64];

    int s = blockIdx.x, h = blockIdx.y, b = blockIdx.z;
    int tid = threadIdx.x;
    int lane64 = tid & 63, quad = tid >> 6;   // 4 partials x 64 lanes

    size_t qbase = (((size_t)b * H_ + h) * (size_t)M_ + (size_t)s * SEG_) * HD_;
    size_t kbase = ((((size_t)0 * B_ + b) * H_ + h) * KVROWS + (size_t)s * TKV_) * HD_;
    size_t vbase = ((((size_t)1 * B_ + b) * H_ + h) * KVROWS + (size_t)s * TKV_) * HD_;

    for (int idx = tid; idx < 64 * 16; idx += 256) {
        int r = idx >> 4, d4 = (idx & 15) << 2;
        float4 kv4 = *(const float4*)&g_kv[kbase + (size_t)r * HD_ + d4];
        Ks[r][d4] = kv4.x; Ks[r][d4 + 1] = kv4.y; Ks[r][d4 + 2] = kv4.z; Ks[r][d4 + 3] = kv4.w;
        float4 vv4 = *(const float4*)&g_kv[vbase + (size_t)r * HD_ + d4];
        Vs[r][d4] = vv4.x; Vs[r][d4 + 1] = vv4.y; Vs[r][d4 + 2] = vv4.z; Vs[r][d4 + 3] = vv4.w;
    }

    int q0 = (tid >> 4) << 2;
    int t0 = (tid & 15) << 2;

    for (int n = 0; n < 2; n++) {
        __syncthreads();
        for (int idx = tid; idx < 64 * 16; idx += 256) {
            int r = idx >> 4, d4 = (idx & 15) << 2;
            float4 q4 = *(const float4*)&g_q[qbase + (size_t)(n * 64 + r) * HD_ + d4];
            Qs[r][d4] = q4.x; Qs[r][d4 + 1] = q4.y; Qs[r][d4 + 2] = q4.z; Qs[r][d4 + 3] = q4.w;
        }
        __syncthreads();

        float acc[4][4];
#pragma unroll
        for (int i = 0; i < 4; i++)
#pragma unroll
            for (int j = 0; j < 4; j++) acc[i][j] = 0.f;
#pragma unroll 8
        for (int kk = 0; kk < 64; kk++) {
            float qa[4], kb[4];
#pragma unroll
            for (int i = 0; i < 4; i++) qa[i] = Qs[q0 + i][kk];
#pragma unroll
            for (int j = 0; j < 4; j++) kb[j] = Ks[t0 + j][kk];
#pragma unroll
            for (int i = 0; i < 4; i++)
#pragma unroll
                for (int j = 0; j < 4; j++) acc[i][j] += qa[i] * kb[j];
        }
#pragma unroll
        for (int i = 0; i < 4; i++)
#pragma unroll
            for (int j = 0; j < 4; j++) Ss[q0 + i][t0 + j] = acc[i][j];
        __syncthreads();

        {   // per-key max over 64-query block: 4 partials x 64 keys
            float mx = -1e30f;
#pragma unroll
            for (int q = quad * 16; q < quad * 16 + 16; q++)
                mx = fmaxf(mx, Ss[q][lane64]);
            part[quad][lane64] = mx;
        }
        __syncthreads();
        if (tid < 64)
            cmax[tid] = fmaxf(fmaxf(part[0][tid], part[1][tid]),
                              fmaxf(part[2][tid], part[3][tid]));
        __syncthreads();

#pragma unroll
        for (int i = 0; i < 4; i++)
#pragma unroll
            for (int j = 0; j < 4; j++)
                Ss[q0 + i][t0 + j] = __expf(acc[i][j] - cmax[t0 + j]);
        __syncthreads();

        {   // per-query denominator: 4 partials x 64 queries
            float sum = 0.f;
#pragma unroll
            for (int t = quad * 16; t < quad * 16 + 16; t++)
                sum += Ss[lane64][t];
            part[quad][lane64] = sum;
        }
        __syncthreads();
        if (tid < 64)
            dsum[tid] = 1e-10f + ((part[0][tid] + part[1][tid])
                                + (part[2][tid] + part[3][tid]));
        __syncthreads();

        float oac[4][4];
#pragma unroll
        for (int i = 0; i < 4; i++)
#pragma unroll
            for (int j = 0; j < 4; j++) oac[i][j] = 0.f;
#pragma unroll 8
        for (int t = 0; t < 64; t++) {
            float wa[4], vb[4];
#pragma unroll
            for (int i = 0; i < 4; i++) wa[i] = Ss[q0 + i][t];
#pragma unroll
            for (int j = 0; j < 4; j++) vb[j] = Vs[t][t0 + j];
#pragma unroll
            for (int i = 0; i < 4; i++)
#pragma unroll
                for (int j = 0; j < 4; j++) oac[i][j] += wa[i] * vb[j];
        }
#pragma unroll
        for (int i = 0; i < 4; i++) {
            int q = q0 + i;
            float inv = 1.0f / dsum[q];
            int m = s * SEG_ + n * 64 + q;
            size_t o = ((size_t)(b * M_ + m)) * DM_ + h * HD_ + t0;
#pragma unroll
            for (int j = 0; j < 4; j++) {
                float v = oac[i][j] * inv;
                __half hv = __float2half(v);
                g_att_hi[o + j] = hv;
                g_att_lo[o + j] = __float2half(v - __half2float(hv));
            }
        }
    }
}

// ---------------------------------------------------------------------------

extern "C" void kernel_launch(void* const* d_in, const int* in_sizes, int n_in,
                              void* d_out, int out_size) {
    const float* x    = (const float*)d_in[0];
    const float* Wqkv = (const float*)d_in[1];
    const float* Wout = (const float*)d_in[2];
    const int*   hmap = (const int*)d_in[3];
    float* out = (float*)d_out;
    (void)in_sizes; (void)n_in; (void)out_size;

    __half *xh, *xl, *qh, *oh, *ah, *al;
    cudaGetSymbolAddress((void**)&xh, g_x_hi);   cudaGetSymbolAddress((void**)&xl, g_x_lo);
    cudaGetSymbolAddress((void**)&qh, g_wqkv_h); cudaGetSymbolAddress((void**)&oh, g_wout_h);
    cudaGetSymbolAddress((void**)&ah, g_att_hi); cudaGetSymbolAddress((void**)&al, g_att_lo);

    // 0) fp16 conversions
    split2_kernel<<<(B_ * M_ * DM_) / 1024, 256>>>(x, xh, xl, B_ * M_ * DM_);
    convert_kernel<<<(3 * DM_ * DM_) / 1024, 256>>>(Wqkv, qh, 3 * DM_ * DM_);
    convert_kernel<<<(DM_ * DM_) / 1024, 256>>>(Wout, oh, DM_ * DM_);

    cudaFuncSetAttribute((const void*)gemm_tc_kernel,
                         cudaFuncAttributeMaxDynamicSharedMemorySize, GEMM_SMEM);

    // 1) Merged Q + KV projection (one launch, 2048 CTAs)
    gemm_tc_kernel<<<2048, 256, GEMM_SMEM>>>(xh, xl, qh, qh + 1024 * 1024,
                                             nullptr, 0, hmap);

    // 2) Hilbert segmented attention
    const int smem = 4 * 64 * 65 * (int)sizeof(float);
    cudaFuncSetAttribute((const void*)hilbert_attn_kernel,
                         cudaFuncAttributeMaxDynamicSharedMemorySize, smem);
    hilbert_attn_kernel<<<dim3(NSEG_, H_, B_), 256, smem>>>();

    // 3) Output projection
    gemm_tc_kernel<<<1024, 256, GEMM_SMEM>>>(ah, al, oh, nullptr, out, 1, hmap);
}

// round 11
// speedup vs baseline: 5.5394x; 1.0892x over previous
#include <cuda_runtime.h>
#include <cuda_fp16.h>
#include <cstdint>

// Problem constants
#define B_    4
#define M_    4096
#define DM_   1024
#define H_    16
#define HD_   64
#define SEG_  128
#define NSEG_ 32
#define TKV_  64
#define KVROWS (NSEG_ * TKV_)
#define SCALE_ 0.125f
#define KDIM  1024

// ---------------------------------------------------------------------------
// Scratch (device globals: allocation-free per harness rules)
// ---------------------------------------------------------------------------
__device__ float g_q[(size_t)B_ * H_ * M_ * HD_];
__device__ float g_kv[(size_t)2 * B_ * H_ * KVROWS * HD_];
__device__ __half g_x_hi[(size_t)B_ * M_ * DM_];
__device__ __half g_x_lo[(size_t)B_ * M_ * DM_];
__device__ __half g_wqkv_h[3 * DM_ * DM_];
__device__ __half g_wout_h[DM_ * DM_];
__device__ __half g_att_h[(size_t)B_ * M_ * DM_];

// ---------------------------------------------------------------------------
// Helpers (compute_103-safe)
// ---------------------------------------------------------------------------
__device__ __forceinline__ uint32_t smem_to_u32(const void* p) {
    uint32_t a;
    asm("{ .reg .u64 t; cvta.to.shared.u64 t, %1; cvt.u32.u64 %0, t; }" : "=r"(a) : "l"(p));
    return a;
}
#define SWZ128(o) ((o) ^ (((o) >> 3) & 0x70))

__device__ __forceinline__ void cp_async16(uint32_t s, const void* g) {
    asm volatile("cp.async.cg.shared.global [%0], [%1], 16;" :: "r"(s), "l"(g));
}
__device__ __forceinline__ void ldsm_x4(uint32_t* r, uint32_t addr) {
    asm volatile("ldmatrix.sync.aligned.m8n8.x4.shared.b16 {%0,%1,%2,%3}, [%4];"
                 : "=r"(r[0]), "=r"(r[1]), "=r"(r[2]), "=r"(r[3]) : "r"(addr));
}
__device__ __forceinline__ void mma16816(float* d, const uint32_t* a, const uint32_t* b) {
    asm volatile("mma.sync.aligned.m16n8k16.row.col.f32.f16.f16.f32 "
                 "{%0,%1,%2,%3}, {%4,%5,%6,%7}, {%8,%9}, {%0,%1,%2,%3};"
                 : "+f"(d[0]), "+f"(d[1]), "+f"(d[2]), "+f"(d[3])
                 : "r"(a[0]), "r"(a[1]), "r"(a[2]), "r"(a[3]), "r"(b[0]), "r"(b[1]));
}

// ---------------------------------------------------------------------------
// fp32 -> fp16 split / convert
// ---------------------------------------------------------------------------
__global__ __launch_bounds__(256) void split2_kernel(const float* __restrict__ in,
                                                     __half* __restrict__ hi,
                                                     __half* __restrict__ lo, int n) {
    int i = (blockIdx.x * 256 + threadIdx.x) * 4;
    if (i >= n) return;
    float4 v = *(const float4*)(in + i);
    __half h0 = __float2half(v.x), h1 = __float2half(v.y);
    __half h2 = __float2half(v.z), h3 = __float2half(v.w);
    __half l0 = __float2half(v.x - __half2float(h0));
    __half l1 = __float2half(v.y - __half2float(h1));
    __half l2 = __float2half(v.z - __half2float(h2));
    __half l3 = __float2half(v.w - __half2float(h3));
    *(__half2*)(hi + i)     = __halves2half2(h0, h1);
    *(__half2*)(hi + i + 2) = __halves2half2(h2, h3);
    *(__half2*)(lo + i)     = __halves2half2(l0, l1);
    *(__half2*)(lo + i + 2) = __halves2half2(l2, l3);
}

__global__ __launch_bounds__(256) void convert_kernel(const float* __restrict__ in,
                                                      __half* __restrict__ out, int n) {
    int i = (blockIdx.x * 256 + threadIdx.x) * 4;
    if (i >= n) return;
    float4 v = *(const float4*)(in + i);
    *(__half2*)(out + i)     = __halves2half2(__float2half(v.x), __float2half(v.y));
    *(__half2*)(out + i + 2) = __halves2half2(__float2half(v.z), __float2half(v.w));
}

// ---------------------------------------------------------------------------
// Tensor-core GEMM, fp16 split (2-term for QKV, 1-term for out), fp32 accum.
// CTA tile 128x128, K-chunk 64, 2-stage cp.async. 8 warps 4(M)x2(N),
// warp tile 32x64 (8 ldsm per 32 MMAs vs 10 for 2x4).
// launch_mode 0: merged Q (blocks 0..1023) + KV (1024..2047), 2 terms.
// launch_mode 1: out projection, 1 term (A_lo skipped entirely).
// ---------------------------------------------------------------------------
#define TILE_SZ   16384u
#define STAGE_SZ  49152u
#define GEMM_SMEM (2 * 49152)

__global__ __launch_bounds__(256, 2) void gemm_tc_kernel(
    const __half* __restrict__ Ahi, const __half* __restrict__ Alo,
    const __half* __restrict__ Bq,  const __half* __restrict__ Bkv,
    float* __restrict__ Cout, int launch_mode, const int* __restrict__ hmap) {
    extern __shared__ char sm[];
    __shared__ int rowmap[128];
    const uint32_t smb = smem_to_u32(sm);
    const int tid = threadIdx.x;
    const int wid = tid >> 5, lane = tid & 31;
    const int wm = wid & 3, wn = wid >> 2;          // 4(M) x 2(N)
    const int nterms = (launch_mode == 0) ? 2 : 1;

    // ---- block -> (epi_mode, m0, n0, B) decode ----
    int epi_mode, m0, n0;
    const __half* Bh;
    if (launch_mode == 0) {
        int bid = blockIdx.x;
        if (bid < 1024) { epi_mode = 0; m0 = (bid >> 3) * 128; n0 = (bid & 7) * 128; Bh = Bq; }
        else { bid -= 1024; epi_mode = 1; m0 = (bid >> 4) * 128; n0 = (bid & 15) * 128; Bh = Bkv; }
    } else {
        epi_mode = 2; m0 = (int)(blockIdx.x >> 3) * 128; n0 = (int)(blockIdx.x & 7) * 128;
        Bh = Bq;
    }

    if (tid < 128) {
        int r;
        if (epi_mode == 0) {
            int bb = m0 >> 12, mq = (m0 & 4095) + tid;
            r = bb * M_ + hmap[mq];
        } else if (epi_mode == 1) {
            int bb = m0 >> 11, rr = (m0 & 2047) + tid;
            int s = rr >> 6, t = rr & 63;
            r = bb * M_ + hmap[s * SEG_ + t * 2];
        } else {
            r = m0 + tid;
        }
        rowmap[tid] = r;
    }
    __syncthreads();

    float acc[2][8][4];
#pragma unroll
    for (int mi = 0; mi < 2; mi++)
#pragma unroll
        for (int ni = 0; ni < 8; ni++)
#pragma unroll
            for (int e = 0; e < 4; e++) acc[mi][ni][e] = 0.f;

    const int a_row = wm * 32 + (lane & 15);                      // + mi*16
    const int a_kb  = (lane >> 4) << 4;
    const int b_row = wn * 64 + ((lane >> 4) << 3) + (lane & 7);  // + p*16
    const int b_kb  = ((lane >> 3) & 1) << 4;

    auto load_chunk = [&](int c, int s) {
        const uint32_t sbase = smb + (uint32_t)s * STAGE_SZ;
#pragma unroll
        for (int tile = 0; tile < 3; tile++) {
            if (tile == 1 && nterms == 1) continue;
            const __half* src = (tile == 0) ? Ahi : (tile == 1) ? Alo : Bh;
#pragma unroll
            for (int tt = 0; tt < 4; tt++) {
                int w = tt * 256 + tid;
                int row = w >> 3, g = (w & 7) << 4;
                int grow = (tile < 2) ? rowmap[row] : (n0 + row);
                const char* gp = (const char*)src
                               + ((size_t)grow * KDIM + (size_t)c * 64) * 2 + g;
                uint32_t off = (uint32_t)(row * 128 + g);
                cp_async16(sbase + (uint32_t)tile * TILE_SZ + SWZ128(off), gp);
            }
        }
        asm volatile("cp.async.commit_group;" ::: "memory");
    };

    load_chunk(0, 0);
    for (int c = 0; c < 16; c++) {
        if (c < 15) {
            load_chunk(c + 1, (c + 1) & 1);
            asm volatile("cp.async.wait_group 1;" ::: "memory");
        } else {
            asm volatile("cp.async.wait_group 0;" ::: "memory");
        }
        __syncthreads();

        const uint32_t sbase = smb + (uint32_t)(c & 1) * STAGE_SZ;
        const uint32_t tA_hi = sbase, tA_lo = sbase + TILE_SZ, tB = sbase + 2 * TILE_SZ;
#pragma unroll
        for (int ks = 0; ks < 4; ks++) {
            uint32_t bhf[4][4];   // 64 N-cols = 4 ldsm.x4 (each: 2 n8k16 frags)
#pragma unroll
            for (int p = 0; p < 4; p++) {
                uint32_t off = (uint32_t)((b_row + p * 16) * 128 + ks * 32 + b_kb);
                ldsm_x4(bhf[p], tB + SWZ128(off));
            }
#pragma unroll
            for (int mi = 0; mi < 2; mi++) {
                uint32_t afh[4];
                uint32_t off = (uint32_t)((a_row + mi * 16) * 128 + ks * 32 + a_kb);
                ldsm_x4(afh, tA_hi + SWZ128(off));
#pragma unroll
                for (int ni = 0; ni < 8; ni++)
                    mma16816(acc[mi][ni], afh, &bhf[ni >> 1][(ni & 1) * 2]);
                if (nterms == 2) {
                    uint32_t afl[4];
                    ldsm_x4(afl, tA_lo + SWZ128(off));
#pragma unroll
                    for (int ni = 0; ni < 8; ni++)
                        mma16816(acc[mi][ni], afl, &bhf[ni >> 1][(ni & 1) * 2]);
                }
            }
        }
        __syncthreads();
    }

    // ---- epilogue ----
    const int ml = wm * 32 + (lane >> 2);
    const int nl = wn * 64 + ((lane & 3) << 1);
#pragma unroll
    for (int mi = 0; mi < 2; mi++)
#pragma unroll
        for (int ni = 0; ni < 8; ni++)
#pragma unroll
            for (int half = 0; half < 2; half++) {
                int row = m0 + ml + mi * 16 + half * 8;
                int col = n0 + nl + ni * 8;
                float2 v = make_float2(acc[mi][ni][half * 2], acc[mi][ni][half * 2 + 1]);
                if (epi_mode == 0) {
                    int hh = col >> 6, d0 = col & 63;
                    int bb = row >> 12, mq = row & 4095;
                    size_t base = (((size_t)bb * H_ + hh) * (size_t)M_ + mq) * HD_ + d0;
                    g_q[base]     = v.x * SCALE_;
                    g_q[base + 1] = v.y * SCALE_;
                } else if (epi_mode == 1) {
                    int which = col >> 10, hh = (col & 1023) >> 6, d0 = col & 63;
                    int bb = row >> 11, rr = row & 2047;
                    size_t base = ((((size_t)which * B_ + bb) * H_ + hh) * KVROWS + rr)
                                  * HD_ + d0;
                    *(float2*)&g_kv[base] = v;
                } else {
                    *(float2*)&Cout[(size_t)row * 1024 + col] = v;
                }
            }
}

// ---------------------------------------------------------------------------
// Attention: one CTA per (segment, head, batch). Contiguous loads, parallel
// reductions. Faithful reference quirk. Emits single fp16 output.
// ---------------------------------------------------------------------------
__global__ __launch_bounds__(256) void hilbert_attn_kernel() {
    extern __shared__ float smf[];
    float (*Qs)[65] = (float (*)[65])(smf);
    float (*Ks)[65] = (float (*)[65])(smf + 64 * 65);
    float (*Vs)[65] = (float (*)[65])(smf + 2 * 64 * 65);
    float (*Ss)[65] = (float (*)[65])(smf + 3 * 64 * 65);
    __shared__ float part[4][64];
    __shared__ float cmax[64];
    __shared__ float dsum[64];

    int s = blockIdx.x, h = blockIdx.y, b = blockIdx.z;
    int tid = threadIdx.x;
    int lane64 = tid & 63, quad = tid >> 6;

    size_t qbase = (((size_t)b * H_ + h) * (size_t)M_ + (size_t)s * SEG_) * HD_;
    size_t kbase = ((((size_t)0 * B_ + b) * H_ + h) * KVROWS + (size_t)s * TKV_) * HD_;
    size_t vbase = ((((size_t)1 * B_ + b) * H_ + h) * KVROWS + (size_t)s * TKV_) * HD_;

    for (int idx = tid; idx < 64 * 16; idx += 256) {
        int r = idx >> 4, d4 = (idx & 15) << 2;
        float4 kv4 = *(const float4*)&g_kv[kbase + (size_t)r * HD_ + d4];
        Ks[r][d4] = kv4.x; Ks[r][d4 + 1] = kv4.y; Ks[r][d4 + 2] = kv4.z; Ks[r][d4 + 3] = kv4.w;
        float4 vv4 = *(const float4*)&g_kv[vbase + (size_t)r * HD_ + d4];
        Vs[r][d4] = vv4.x; Vs[r][d4 + 1] = vv4.y; Vs[r][d4 + 2] = vv4.z; Vs[r][d4 + 3] = vv4.w;
    }

    int q0 = (tid >> 4) << 2;
    int t0 = (tid & 15) << 2;

    for (int n = 0; n < 2; n++) {
        __syncthreads();
        for (int idx = tid; idx < 64 * 16; idx += 256) {
            int r = idx >> 4, d4 = (idx & 15) << 2;
            float4 q4 = *(const float4*)&g_q[qbase + (size_t)(n * 64 + r) * HD_ + d4];
            Qs[r][d4] = q4.x; Qs[r][d4 + 1] = q4.y; Qs[r][d4 + 2] = q4.z; Qs[r][d4 + 3] = q4.w;
        }
        __syncthreads();

        float acc[4][4];
#pragma unroll
        for (int i = 0; i < 4; i++)
#pragma unroll
            for (int j = 0; j < 4; j++) acc[i][j] = 0.f;
#pragma unroll 8
        for (int kk = 0; kk < 64; kk++) {
            float qa[4], kb[4];
#pragma unroll
            for (int i = 0; i < 4; i++) qa[i] = Qs[q0 + i][kk];
#pragma unroll
            for (int j = 0; j < 4; j++) kb[j] = Ks[t0 + j][kk];
#pragma unroll
            for (int i = 0; i < 4; i++)
#pragma unroll
                for (int j = 0; j < 4; j++) acc[i][j] += qa[i] * kb[j];
        }
#pragma unroll
        for (int i = 0; i < 4; i++)
#pragma unroll
            for (int j = 0; j < 4; j++) Ss[q0 + i][t0 + j] = acc[i][j];
        __syncthreads();

        {
            float mx = -1e30f;
#pragma unroll
            for (int q = quad * 16; q < quad * 16 + 16; q++)
                mx = fmaxf(mx, Ss[q][lane64]);
            part[quad][lane64] = mx;
        }
        __syncthreads();
        if (tid < 64)
            cmax[tid] = fmaxf(fmaxf(part[0][tid], part[1][tid]),
                              fmaxf(part[2][tid], part[3][tid]));
        __syncthreads();

#pragma unroll
        for (int i = 0; i < 4; i++)
#pragma unroll
            for (int j = 0; j < 4; j++)
                Ss[q0 + i][t0 + j] = __expf(acc[i][j] - cmax[t0 + j]);
        __syncthreads();

        {
            float sum = 0.f;
#pragma unroll
            for (int t = quad * 16; t < quad * 16 + 16; t++)
                sum += Ss[lane64][t];
            part[quad][lane64] = sum;
        }
        __syncthreads();
        if (tid < 64)
            dsum[tid] = 1e-10f + ((part[0][tid] + part[1][tid])
                                + (part[2][tid] + part[3][tid]));
        __syncthreads();

        float oac[4][4];
#pragma unroll
        for (int i = 0; i < 4; i++)
#pragma unroll
            for (int j = 0; j < 4; j++) oac[i][j] = 0.f;
#pragma unroll 8
        for (int t = 0; t < 64; t++) {
            float wa[4], vb[4];
#pragma unroll
            for (int i = 0; i < 4; i++) wa[i] = Ss[q0 + i][t];
#pragma unroll
            for (int j = 0; j < 4; j++) vb[j] = Vs[t][t0 + j];
#pragma unroll
            for (int i = 0; i < 4; i++)
#pragma unroll
                for (int j = 0; j < 4; j++) oac[i][j] += wa[i] * vb[j];
        }
#pragma unroll
        for (int i = 0; i < 4; i++) {
            int q = q0 + i;
            float inv = 1.0f / dsum[q];
            int m = s * SEG_ + n * 64 + q;
            size_t o = ((size_t)(b * M_ + m)) * DM_ + h * HD_ + t0;
            __half2 p0 = __halves2half2(__float2half(oac[i][0] * inv),
                                        __float2half(oac[i][1] * inv));
            __half2 p1 = __halves2half2(__float2half(oac[i][2] * inv),
                                        __float2half(oac[i][3] * inv));
            *(__half2*)&g_att_h[o]     = p0;
            *(__half2*)&g_att_h[o + 2] = p1;
        }
    }
}

// ---------------------------------------------------------------------------

extern "C" void kernel_launch(void* const* d_in, const int* in_sizes, int n_in,
                              void* d_out, int out_size) {
    const float* x    = (const float*)d_in[0];
    const float* Wqkv = (const float*)d_in[1];
    const float* Wout = (const float*)d_in[2];
    const int*   hmap = (const int*)d_in[3];
    float* out = (float*)d_out;
    (void)in_sizes; (void)n_in; (void)out_size;

    __half *xh, *xl, *qh, *oh, *ah;
    cudaGetSymbolAddress((void**)&xh, g_x_hi);   cudaGetSymbolAddress((void**)&xl, g_x_lo);
    cudaGetSymbolAddress((void**)&qh, g_wqkv_h); cudaGetSymbolAddress((void**)&oh, g_wout_h);
    cudaGetSymbolAddress((void**)&ah, g_att_h);

    // 0) fp16 conversions
    split2_kernel<<<(B_ * M_ * DM_) / 1024, 256>>>(x, xh, xl, B_ * M_ * DM_);
    convert_kernel<<<(3 * DM_ * DM_) / 1024, 256>>>(Wqkv, qh, 3 * DM_ * DM_);
    convert_kernel<<<(DM_ * DM_) / 1024, 256>>>(Wout, oh, DM_ * DM_);

    cudaFuncSetAttribute((const void*)gemm_tc_kernel,
                         cudaFuncAttributeMaxDynamicSharedMemorySize, GEMM_SMEM);

    // 1) Merged Q + KV projection (2048 CTAs, 2-term)
    gemm_tc_kernel<<<2048, 256, GEMM_SMEM>>>(xh, xl, qh, qh + 1024 * 1024,
                                             nullptr, 0, hmap);

    // 2) Hilbert segmented attention
    const int smem = 4 * 64 * 65 * (int)sizeof(float);
    cudaFuncSetAttribute((const void*)hilbert_attn_kernel,
                         cudaFuncAttributeMaxDynamicSharedMemorySize, smem);
    hilbert_attn_kernel<<<dim3(NSEG_, H_, B_), 256, smem>>>();

    // 3) Output projection (1024 CTAs, 1-term)
    gemm_tc_kernel<<<1024, 256, GEMM_SMEM>>>(ah, nullptr, oh, nullptr, out, 1, hmap);
}

// round 12
// speedup vs baseline: 5.7804x; 1.0435x over previous
#include <cuda_runtime.h>
#include <cuda_fp16.h>
#include <cstdint>

// Problem constants
#define B_    4
#define M_    4096
#define DM_   1024
#define H_    16
#define HD_   64
#define SEG_  128
#define NSEG_ 32
#define TKV_  64
#define KVROWS (NSEG_ * TKV_)
#define SCALE_ 0.125f
#define KDIM  1024

// ---------------------------------------------------------------------------
// Scratch (device globals: allocation-free per harness rules)
// ---------------------------------------------------------------------------
__device__ __half g_q[(size_t)B_ * H_ * M_ * HD_];                // fp16, scaled, hmap-ordered
__device__ __half g_kv[(size_t)2 * B_ * H_ * KVROWS * HD_];       // fp16
__device__ __half g_x_hi[(size_t)B_ * M_ * DM_];
__device__ __half g_x_lo[(size_t)B_ * M_ * DM_];
__device__ __half g_wqkv_h[3 * DM_ * DM_];
__device__ __half g_wout_h[DM_ * DM_];
__device__ __half g_att_h[(size_t)B_ * M_ * DM_];

// ---------------------------------------------------------------------------
// Helpers (compute_103-safe)
// ---------------------------------------------------------------------------
__device__ __forceinline__ uint32_t smem_to_u32(const void* p) {
    uint32_t a;
    asm("{ .reg .u64 t; cvta.to.shared.u64 t, %1; cvt.u32.u64 %0, t; }" : "=r"(a) : "l"(p));
    return a;
}
#define SWZ128(o) ((o) ^ (((o) >> 3) & 0x70))

__device__ __forceinline__ void cp_async16(uint32_t s, const void* g) {
    asm volatile("cp.async.cg.shared.global [%0], [%1], 16;" :: "r"(s), "l"(g));
}
__device__ __forceinline__ void ldsm_x4(uint32_t* r, uint32_t addr) {
    asm volatile("ldmatrix.sync.aligned.m8n8.x4.shared.b16 {%0,%1,%2,%3}, [%4];"
                 : "=r"(r[0]), "=r"(r[1]), "=r"(r[2]), "=r"(r[3]) : "r"(addr));
}
__device__ __forceinline__ void mma16816(float* d, const uint32_t* a, const uint32_t* b) {
    asm volatile("mma.sync.aligned.m16n8k16.row.col.f32.f16.f16.f32 "
                 "{%0,%1,%2,%3}, {%4,%5,%6,%7}, {%8,%9}, {%0,%1,%2,%3};"
                 : "+f"(d[0]), "+f"(d[1]), "+f"(d[2]), "+f"(d[3])
                 : "r"(a[0]), "r"(a[1]), "r"(a[2]), "r"(a[3]), "r"(b[0]), "r"(b[1]));
}

// ---------------------------------------------------------------------------
// Merged conversion kernel: x split (blocks 0..16383), Wqkv convert
// (16384..19455), Wout convert (19456..20479). 1024 elements per block.
// ---------------------------------------------------------------------------
__global__ __launch_bounds__(256) void prep_kernel(const float* __restrict__ x,
                                                   const float* __restrict__ Wqkv,
                                                   const float* __restrict__ Wout) {
    int bid = blockIdx.x;
    int t4 = threadIdx.x * 4;
    if (bid < 16384) {
        int i = bid * 1024 + t4;
        float4 v = *(const float4*)(x + i);
        __half h0 = __float2half(v.x), h1 = __float2half(v.y);
        __half h2 = __float2half(v.z), h3 = __float2half(v.w);
        *(__half2*)(g_x_hi + i)     = __halves2half2(h0, h1);
        *(__half2*)(g_x_hi + i + 2) = __halves2half2(h2, h3);
        *(__half2*)(g_x_lo + i)     = __halves2half2(__float2half(v.x - __half2float(h0)),
                                                     __float2half(v.y - __half2float(h1)));
        *(__half2*)(g_x_lo + i + 2) = __halves2half2(__float2half(v.z - __half2float(h2)),
                                                     __float2half(v.w - __half2float(h3)));
    } else if (bid < 19456) {
        int i = (bid - 16384) * 1024 + t4;
        float4 v = *(const float4*)(Wqkv + i);
        *(__half2*)(g_wqkv_h + i)     = __halves2half2(__float2half(v.x), __float2half(v.y));
        *(__half2*)(g_wqkv_h + i + 2) = __halves2half2(__float2half(v.z), __float2half(v.w));
    } else {
        int i = (bid - 19456) * 1024 + t4;
        float4 v = *(const float4*)(Wout + i);
        *(__half2*)(g_wout_h + i)     = __halves2half2(__float2half(v.x), __float2half(v.y));
        *(__half2*)(g_wout_h + i + 2) = __halves2half2(__float2half(v.z), __float2half(v.w));
    }
}

// ---------------------------------------------------------------------------
// Tensor-core GEMM, fp16 split (2-term QKV, 1-term out), fp32 accum.
// CTA tile 128x128, K-chunk 64, 2-stage cp.async. 8 warps 2(M)x4(N),
// warp tile 64x32 (the R10 layout — measured best).
// launch_mode 0: merged Q (blocks 0..1023) + KV (1024..2047), 2 terms.
// launch_mode 1: out projection, 1 term.
// ---------------------------------------------------------------------------
#define TILE_SZ   16384u
#define STAGE_SZ  49152u
#define GEMM_SMEM (2 * 49152)

__global__ __launch_bounds__(256, 2) void gemm_tc_kernel(
    const __half* __restrict__ Ahi, const __half* __restrict__ Alo,
    const __half* __restrict__ Bq,  const __half* __restrict__ Bkv,
    float* __restrict__ Cout, int launch_mode, const int* __restrict__ hmap) {
    extern __shared__ char sm[];
    __shared__ int rowmap[128];
    const uint32_t smb = smem_to_u32(sm);
    const int tid = threadIdx.x;
    const int wid = tid >> 5, lane = tid & 31;
    const int wm = wid & 1, wn = wid >> 1;          // 2(M) x 4(N)
    const int nterms = (launch_mode == 0) ? 2 : 1;

    int epi_mode, m0, n0;
    const __half* Bh;
    if (launch_mode == 0) {
        int bid = blockIdx.x;
        if (bid < 1024) { epi_mode = 0; m0 = (bid >> 3) * 128; n0 = (bid & 7) * 128; Bh = Bq; }
        else { bid -= 1024; epi_mode = 1; m0 = (bid >> 4) * 128; n0 = (bid & 15) * 128; Bh = Bkv; }
    } else {
        epi_mode = 2; m0 = (int)(blockIdx.x >> 3) * 128; n0 = (int)(blockIdx.x & 7) * 128;
        Bh = Bq;
    }

    if (tid < 128) {
        int r;
        if (epi_mode == 0) {
            int bb = m0 >> 12, mq = (m0 & 4095) + tid;
            r = bb * M_ + hmap[mq];
        } else if (epi_mode == 1) {
            int bb = m0 >> 11, rr = (m0 & 2047) + tid;
            int s = rr >> 6, t = rr & 63;
            r = bb * M_ + hmap[s * SEG_ + t * 2];
        } else {
            r = m0 + tid;
        }
        rowmap[tid] = r;
    }
    __syncthreads();

    float acc[4][4][4];
#pragma unroll
    for (int mi = 0; mi < 4; mi++)
#pragma unroll
        for (int ni = 0; ni < 4; ni++)
#pragma unroll
            for (int e = 0; e < 4; e++) acc[mi][ni][e] = 0.f;

    const int a_row = wm * 64 + (lane & 15);
    const int a_kb  = (lane >> 4) << 4;
    const int b_row = wn * 32 + ((lane >> 4) << 3) + (lane & 7);
    const int b_kb  = ((lane >> 3) & 1) << 4;

    auto load_chunk = [&](int c, int s) {
        const uint32_t sbase = smb + (uint32_t)s * STAGE_SZ;
#pragma unroll
        for (int tile = 0; tile < 3; tile++) {
            if (tile == 1 && nterms == 1) continue;
            const __half* src = (tile == 0) ? Ahi : (tile == 1) ? Alo : Bh;
#pragma unroll
            for (int tt = 0; tt < 4; tt++) {
                int w = tt * 256 + tid;
                int row = w >> 3, g = (w & 7) << 4;
                int grow = (tile < 2) ? rowmap[row] : (n0 + row);
                const char* gp = (const char*)src
                               + ((size_t)grow * KDIM + (size_t)c * 64) * 2 + g;
                uint32_t off = (uint32_t)(row * 128 + g);
                cp_async16(sbase + (uint32_t)tile * TILE_SZ + SWZ128(off), gp);
            }
        }
        asm volatile("cp.async.commit_group;" ::: "memory");
    };

    load_chunk(0, 0);
    for (int c = 0; c < 16; c++) {
        if (c < 15) {
            load_chunk(c + 1, (c + 1) & 1);
            asm volatile("cp.async.wait_group 1;" ::: "memory");
        } else {
            asm volatile("cp.async.wait_group 0;" ::: "memory");
        }
        __syncthreads();

        const uint32_t sbase = smb + (uint32_t)(c & 1) * STAGE_SZ;
        const uint32_t tA_hi = sbase, tA_lo = sbase + TILE_SZ, tB = sbase + 2 * TILE_SZ;
#pragma unroll
        for (int ks = 0; ks < 4; ks++) {
            uint32_t bhf[2][4];
#pragma unroll
            for (int p = 0; p < 2; p++) {
                uint32_t off = (uint32_t)((b_row + p * 16) * 128 + ks * 32 + b_kb);
                ldsm_x4(bhf[p], tB + SWZ128(off));
            }
            // interleaved hi/lo per mi: next mi's ldsm overlaps current MMAs
#pragma unroll
            for (int mi = 0; mi < 4; mi++) {
                uint32_t afh[4];
                uint32_t off = (uint32_t)((a_row + mi * 16) * 128 + ks * 32 + a_kb);
                ldsm_x4(afh, tA_hi + SWZ128(off));
                if (nterms == 2) {
                    uint32_t afl[4];
                    ldsm_x4(afl, tA_lo + SWZ128(off));
#pragma unroll
                    for (int ni = 0; ni < 4; ni++)
                        mma16816(acc[mi][ni], afh, &bhf[ni >> 1][(ni & 1) * 2]);
#pragma unroll
                    for (int ni = 0; ni < 4; ni++)
                        mma16816(acc[mi][ni], afl, &bhf[ni >> 1][(ni & 1) * 2]);
                } else {
#pragma unroll
                    for (int ni = 0; ni < 4; ni++)
                        mma16816(acc[mi][ni], afh, &bhf[ni >> 1][(ni & 1) * 2]);
                }
            }
        }
        __syncthreads();
    }

    // ---- epilogue ----
    const int ml = wm * 64 + (lane >> 2);
    const int nl = wn * 32 + ((lane & 3) << 1);
#pragma unroll
    for (int mi = 0; mi < 4; mi++)
#pragma unroll
        for (int ni = 0; ni < 4; ni++)
#pragma unroll
            for (int half = 0; half < 2; half++) {
                int row = m0 + ml + mi * 16 + half * 8;
                int col = n0 + nl + ni * 8;
                float2 v = make_float2(acc[mi][ni][half * 2], acc[mi][ni][half * 2 + 1]);
                if (epi_mode == 0) {
                    int hh = col >> 6, d0 = col & 63;
                    int bb = row >> 12, mq = row & 4095;
                    size_t base = (((size_t)bb * H_ + hh) * (size_t)M_ + mq) * HD_ + d0;
                    *(__half2*)&g_q[base] = __halves2half2(__float2half(v.x * SCALE_),
                                                           __float2half(v.y * SCALE_));
                } else if (epi_mode == 1) {
                    int which = col >> 10, hh = (col & 1023) >> 6, d0 = col & 63;
                    int bb = row >> 11, rr = row & 2047;
                    size_t base = ((((size_t)which * B_ + bb) * H_ + hh) * KVROWS + rr)
                                  * HD_ + d0;
                    *(__half2*)&g_kv[base] = __halves2half2(__float2half(v.x),
                                                            __float2half(v.y));
                } else {
                    *(float2*)&Cout[(size_t)row * 1024 + col] = v;
                }
            }
}

// ---------------------------------------------------------------------------
// Attention: one CTA per (segment, head, batch). fp16 global loads converted
// to fp32 in smem; compute fp32. Faithful reference quirk preserved.
// ---------------------------------------------------------------------------
__global__ __launch_bounds__(256) void hilbert_attn_kernel() {
    extern __shared__ float smf[];
    float (*Qs)[65] = (float (*)[65])(smf);
    float (*Ks)[65] = (float (*)[65])(smf + 64 * 65);
    float (*Vs)[65] = (float (*)[65])(smf + 2 * 64 * 65);
    float (*Ss)[65] = (float (*)[65])(smf + 3 * 64 * 65);
    __shared__ float part[4][64];
    __shared__ float cmax[64];
    __shared__ float dsum[64];

    int s = blockIdx.x, h = blockIdx.y, b = blockIdx.z;
    int tid = threadIdx.x;
    int lane64 = tid & 63, quad = tid >> 6;

    size_t qbase = (((size_t)b * H_ + h) * (size_t)M_ + (size_t)s * SEG_) * HD_;
    size_t kbase = ((((size_t)0 * B_ + b) * H_ + h) * KVROWS + (size_t)s * TKV_) * HD_;
    size_t vbase = ((((size_t)1 * B_ + b) * H_ + h) * KVROWS + (size_t)s * TKV_) * HD_;

    // K/V: 64 rows x 64 halves = 512 uint4 (8 halves each)
    for (int idx = tid; idx < 512; idx += 256) {
        int r = idx >> 3, d8 = (idx & 7) << 3;
        uint4 kraw = *(const uint4*)&g_kv[kbase + (size_t)r * HD_ + d8];
        const __half2* kp = (const __half2*)&kraw;
#pragma unroll
        for (int j = 0; j < 4; j++) {
            float2 f = __half22float2(kp[j]);
            Ks[r][d8 + j * 2] = f.x; Ks[r][d8 + j * 2 + 1] = f.y;
        }
        uint4 vraw = *(const uint4*)&g_kv[vbase + (size_t)r * HD_ + d8];
        const __half2* vp = (const __half2*)&vraw;
#pragma unroll
        for (int j = 0; j < 4; j++) {
            float2 f = __half22float2(vp[j]);
            Vs[r][d8 + j * 2] = f.x; Vs[r][d8 + j * 2 + 1] = f.y;
        }
    }

    int q0 = (tid >> 4) << 2;
    int t0 = (tid & 15) << 2;

    for (int n = 0; n < 2; n++) {
        __syncthreads();
        for (int idx = tid; idx < 512; idx += 256) {
            int r = idx >> 3, d8 = (idx & 7) << 3;
            uint4 qraw = *(const uint4*)&g_q[qbase + (size_t)(n * 64 + r) * HD_ + d8];
            const __half2* qp = (const __half2*)&qraw;
#pragma unroll
            for (int j = 0; j < 4; j++) {
                float2 f = __half22float2(qp[j]);
                Qs[r][d8 + j * 2] = f.x; Qs[r][d8 + j * 2 + 1] = f.y;
            }
        }
        __syncthreads();

        float acc[4][4];
#pragma unroll
        for (int i = 0; i < 4; i++)
#pragma unroll
            for (int j = 0; j < 4; j++) acc[i][j] = 0.f;
#pragma unroll 8
        for (int kk = 0; kk < 64; kk++) {
            float qa[4], kb[4];
#pragma unroll
            for (int i = 0; i < 4; i++) qa[i] = Qs[q0 + i][kk];
#pragma unroll
            for (int j = 0; j < 4; j++) kb[j] = Ks[t0 + j][kk];
#pragma unroll
            for (int i = 0; i < 4; i++)
#pragma unroll
                for (int j = 0; j < 4; j++) acc[i][j] += qa[i] * kb[j];
        }
#pragma unroll
        for (int i = 0; i < 4; i++)
#pragma unroll
            for (int j = 0; j < 4; j++) Ss[q0 + i][t0 + j] = acc[i][j];
        __syncthreads();

        {
            float mx = -1e30f;
#pragma unroll
            for (int q = quad * 16; q < quad * 16 + 16; q++)
                mx = fmaxf(mx, Ss[q][lane64]);
            part[quad][lane64] = mx;
        }
        __syncthreads();
        if (tid < 64)
            cmax[tid] = fmaxf(fmaxf(part[0][tid], part[1][tid]),
                              fmaxf(part[2][tid], part[3][tid]));
        __syncthreads();

#pragma unroll
        for (int i = 0; i < 4; i++)
#pragma unroll
            for (int j = 0; j < 4; j++)
                Ss[q0 + i][t0 + j] = __expf(acc[i][j] - cmax[t0 + j]);
        __syncthreads();

        {
            float sum = 0.f;
#pragma unroll
            for (int t = quad * 16; t < quad * 16 + 16; t++)
                sum += Ss[lane64][t];
            part[quad][lane64] = sum;
        }
        __syncthreads();
        if (tid < 64)
            dsum[tid] = 1e-10f + ((part[0][tid] + part[1][tid])
                                + (part[2][tid] + part[3][tid]));
        __syncthreads();

        float oac[4][4];
#pragma unroll
        for (int i = 0; i < 4; i++)
#pragma unroll
            for (int j = 0; j < 4; j++) oac[i][j] = 0.f;
#pragma unroll 8
        for (int t = 0; t < 64; t++) {
            float wa[4], vb[4];
#pragma unroll
            for (int i = 0; i < 4; i++) wa[i] = Ss[q0 + i][t];
#pragma unroll
            for (int j = 0; j < 4; j++) vb[j] = Vs[t][t0 + j];
#pragma unroll
            for (int i = 0; i < 4; i++)
#pragma unroll
                for (int j = 0; j < 4; j++) oac[i][j] += wa[i] * vb[j];
        }
#pragma unroll
        for (int i = 0; i < 4; i++) {
            int q = q0 + i;
            float inv = 1.0f / dsum[q];
            int m = s * SEG_ + n * 64 + q;
            size_t o = ((size_t)(b * M_ + m)) * DM_ + h * HD_ + t0;
            *(__half2*)&g_att_h[o]     = __halves2half2(__float2half(oac[i][0] * inv),
                                                        __float2half(oac[i][1] * inv));
            *(__half2*)&g_att_h[o + 2] = __halves2half2(__float2half(oac[i][2] * inv),
                                                        __float2half(oac[i][3] * inv));
        }
    }
}

// ---------------------------------------------------------------------------

extern "C" void kernel_launch(void* const* d_in, const int* in_sizes, int n_in,
                              void* d_out, int out_size) {
    const float* x    = (const float*)d_in[0];
    const float* Wqkv = (const float*)d_in[1];
    const float* Wout = (const float*)d_in[2];
    const int*   hmap = (const int*)d_in[3];
    float* out = (float*)d_out;
    (void)in_sizes; (void)n_in; (void)out_size;

    __half *xh, *xl, *qh, *oh, *ah;
    cudaGetSymbolAddress((void**)&xh, g_x_hi);   cudaGetSymbolAddress((void**)&xl, g_x_lo);
    cudaGetSymbolAddress((void**)&qh, g_wqkv_h); cudaGetSymbolAddress((void**)&oh, g_wout_h);
    cudaGetSymbolAddress((void**)&ah, g_att_h);

    // 0) merged fp16 conversions (x split + Wqkv + Wout)
    prep_kernel<<<20480, 256>>>(x, Wqkv, Wout);

    cudaFuncSetAttribute((const void*)gemm_tc_kernel,
                         cudaFuncAttributeMaxDynamicSharedMemorySize, GEMM_SMEM);

    // 1) Merged Q + KV projection (2048 CTAs, 2-term)
    gemm_tc_kernel<<<2048, 256, GEMM_SMEM>>>(xh, xl, qh, qh + 1024 * 1024,
                                             nullptr, 0, hmap);

    // 2) Hilbert segmented attention
    const int smem = 4 * 64 * 65 * (int)sizeof(float);
    cudaFuncSetAttribute((const void*)hilbert_attn_kernel,
                         cudaFuncAttributeMaxDynamicSharedMemorySize, smem);
    hilbert_attn_kernel<<<dim3(NSEG_, H_, B_), 256, smem>>>();

    // 3) Output projection (1024 CTAs, 1-term)
    gemm_tc_kernel<<<1024, 256, GEMM_SMEM>>>(ah, nullptr, oh, nullptr, out, 1, hmap);
}